// round 1
// baseline (speedup 1.0000x reference)
#include <cuda_runtime.h>
#include <math.h>

#define BB 2
#define LL 48
#define NN 3000
#define DD 128
#define L_OUT 24
#define BNN (BB*NN)          // 6000
#define BLL (BB*LL)          // 96
#define ROWS (BNN*LL)        // 288000 token rows
#define ENC_N (ROWS*DD)      // 36,864,000

// ---------------- scratch (device globals; no runtime allocation) ----------------
__device__ float d_mean[BNN];
__device__ float d_peT[DD*NN];           // peT[d][n]
__device__ float d_WT2[DD*DD*DD];        // WT2[(i*128+o)][d] = wp[d][i][o]
__device__ float d_pe2[NN*DD];           // pe2[n][d]
__device__ float d_enc[ENC_N];           // enc[seq][l][c], seq = b*NN+n
__device__ float d_h[ENC_N];             // LN output (reused for LN2)
__device__ float d_qb[ENC_N];
__device__ float d_kb[ENC_N];
__device__ float d_vb[ENC_N];
__device__ float d_ff[ROWS*512];         // gelu intermediate
__device__ float d_X[BLL*DD*NN];         // X[(bl*128+d)][n] = enc[(b,n)][l][d]
__device__ float d_agg[NN*BLL*DD];       // agg[n][bl][i]
__device__ float d_pw[NN*DD*DD];         // pw[n][i][o]
__device__ float d_gout[NN*BLL*DD];      // gout[n][bl][o]
__device__ float d_gmu[BLL*4];
__device__ float d_grs[BLL*4];

__device__ __forceinline__ float gelu_exact(float x) {
    return 0.5f * x * (1.0f + erff(x * 0.70710678118654752f));
}

// ---------------- small prep kernels ----------------
__global__ void k_mean(const float* __restrict__ x) {
    int i = blockIdx.x * blockDim.x + threadIdx.x;
    if (i >= BNN) return;
    int b = i / NN, n = i % NN;
    float s = 0.f;
    #pragma unroll
    for (int l = 0; l < LL; ++l) s += x[(b*LL + l)*NN + n];
    d_mean[i] = s * (1.0f / LL);
}

__global__ void k_peT(const float* __restrict__ pr, const float* __restrict__ pw,
                      const float* __restrict__ pb) {
    int i = blockIdx.x * blockDim.x + threadIdx.x;
    if (i >= DD*NN) return;
    int d = i / NN, n = i % NN;
    d_peT[i] = pr[n]*pw[d*3] + pr[NN+n]*pw[d*3+1] + pr[2*NN+n]*pw[d*3+2] + pb[d];
}

__global__ void k_WT2(const float* __restrict__ wp) {
    int idx = blockIdx.x * blockDim.x + threadIdx.x;
    if (idx >= DD*DD*DD) return;
    int d = idx & 127;
    int io = idx >> 7;
    int o = io & 127, ii = io >> 7;
    d_WT2[idx] = wp[(d*128 + ii)*128 + o];
}

// circular conv1d k=3: enc[seq][l][c]
__global__ void k_conv(const float* __restrict__ x, const float* __restrict__ cw) {
    __shared__ float xs[LL + 2];
    int seq = blockIdx.x;
    int b = seq / NN, n = seq % NN;
    float m = d_mean[seq];
    int t = threadIdx.x;   // 128
    if (t < LL) xs[t + 1] = x[(b*LL + t)*NN + n] - m;
    __syncthreads();
    if (t == 0) { xs[0] = xs[LL]; xs[LL+1] = xs[1]; }
    __syncthreads();
    float w0 = cw[t*3], w1 = cw[t*3+1], w2 = cw[t*3+2];
    float* out = d_enc + (size_t)seq * (LL*DD);
    #pragma unroll
    for (int l = 0; l < LL; ++l)
        out[l*DD + t] = w0*xs[l] + w1*xs[l+1] + w2*xs[l+2];
}

// LayerNorm over rows of 128 (one warp per row)
__global__ void k_ln(const float* __restrict__ X, float* __restrict__ Y,
                     const float* __restrict__ g, const float* __restrict__ bta) {
    int warp = (blockIdx.x * blockDim.x + threadIdx.x) >> 5;
    int lane = threadIdx.x & 31;
    const float* xr = X + (size_t)warp * DD;
    float4 v = *(const float4*)(xr + lane*4);
    float s = v.x + v.y + v.z + v.w;
    float sq = v.x*v.x + v.y*v.y + v.z*v.z + v.w*v.w;
    #pragma unroll
    for (int o = 16; o; o >>= 1) {
        s  += __shfl_xor_sync(~0u, s, o);
        sq += __shfl_xor_sync(~0u, sq, o);
    }
    float mu = s * (1.0f/DD);
    float var = sq * (1.0f/DD) - mu*mu;
    float rs = rsqrtf(var + 1e-5f);
    float4 gg = *(const float4*)(g + lane*4);
    float4 bb = *(const float4*)(bta + lane*4);
    float4 o4;
    o4.x = (v.x - mu)*rs*gg.x + bb.x;
    o4.y = (v.y - mu)*rs*gg.y + bb.y;
    o4.z = (v.z - mu)*rs*gg.z + bb.z;
    o4.w = (v.w - mu)*rs*gg.w + bb.w;
    *(float4*)(Y + (size_t)warp*DD + lane*4) = o4;
}

// softmax over feature dim (rows of 128), then * sc
__global__ void k_smax_row(float* __restrict__ X, float sc) {
    int warp = (blockIdx.x * blockDim.x + threadIdx.x) >> 5;
    int lane = threadIdx.x & 31;
    float* xr = X + (size_t)warp * DD;
    float4 v = *(float4*)(xr + lane*4);
    float mx = fmaxf(fmaxf(v.x, v.y), fmaxf(v.z, v.w));
    #pragma unroll
    for (int o = 16; o; o >>= 1) mx = fmaxf(mx, __shfl_xor_sync(~0u, mx, o));
    v.x = expf(v.x - mx); v.y = expf(v.y - mx);
    v.z = expf(v.z - mx); v.w = expf(v.w - mx);
    float s = v.x + v.y + v.z + v.w;
    #pragma unroll
    for (int o = 16; o; o >>= 1) s += __shfl_xor_sync(~0u, s, o);
    float f = sc / s;
    v.x *= f; v.y *= f; v.z *= f; v.w *= f;
    *(float4*)(xr + lane*4) = v;
}

// softmax over L (axis=1) per (seq, feature)
__global__ void k_smax_col(float* __restrict__ X) {
    int seq = blockIdx.x;
    int c = threadIdx.x;     // 128
    float* p = X + (size_t)seq * (LL*DD) + c;
    float v[LL];
    float mx = -1e30f;
    #pragma unroll
    for (int l = 0; l < LL; ++l) { v[l] = p[l*DD]; mx = fmaxf(mx, v[l]); }
    float s = 0.f;
    #pragma unroll
    for (int l = 0; l < LL; ++l) { v[l] = expf(v[l] - mx); s += v[l]; }
    float inv = 1.0f / s;
    #pragma unroll
    for (int l = 0; l < LL; ++l) p[l*DD] = v[l] * inv;
}

// ---------------- fused linear attention per sequence ----------------
// ctx = kk^T @ v ; att = q @ ctx ; enc += att @ wo^T
#define WPAD 132
#define ATTN_SMEM ((6144*3 + 128*WPAD) * 4)
__global__ void __launch_bounds__(256, 1) k_attn(const float* __restrict__ wo) {
    extern __shared__ float sm[];
    float* Q  = sm;
    float* KK = sm + 6144;     // later reused for att_pre
    float* V  = sm + 12288;
    float* W  = sm + 18432;    // 128 x WPAD (ctx, then wo^T)
    int seq = blockIdx.x, tid = threadIdx.x;
    size_t base = (size_t)seq * 6144;
    for (int i = tid; i < 6144; i += 256) {
        Q[i] = d_qb[base+i]; KK[i] = d_kb[base+i]; V[i] = d_vb[base+i];
    }
    __syncthreads();
    int te = tid & 31, tg = tid >> 5;
    // ctx[dd][e] = sum_l KK[l][dd]*V[l][e]
    #pragma unroll
    for (int it = 0; it < 4; ++it) {
        int dd0 = (tg + it*8) * 4, e0 = te * 4;
        float a[4][4] = {};
        #pragma unroll
        for (int l = 0; l < LL; ++l) {
            float4 kf = *(float4*)&KK[l*128 + dd0];
            float4 vf = *(float4*)&V[l*128 + e0];
            a[0][0]+=kf.x*vf.x; a[0][1]+=kf.x*vf.y; a[0][2]+=kf.x*vf.z; a[0][3]+=kf.x*vf.w;
            a[1][0]+=kf.y*vf.x; a[1][1]+=kf.y*vf.y; a[1][2]+=kf.y*vf.z; a[1][3]+=kf.y*vf.w;
            a[2][0]+=kf.z*vf.x; a[2][1]+=kf.z*vf.y; a[2][2]+=kf.z*vf.z; a[2][3]+=kf.z*vf.w;
            a[3][0]+=kf.w*vf.x; a[3][1]+=kf.w*vf.y; a[3][2]+=kf.w*vf.z; a[3][3]+=kf.w*vf.w;
        }
        #pragma unroll
        for (int j = 0; j < 4; ++j)
            *(float4*)&W[(dd0+j)*WPAD + e0] = make_float4(a[j][0], a[j][1], a[j][2], a[j][3]);
    }
    __syncthreads();
    // att_pre[l][e] = sum_dd Q[l][dd]*ctx[dd][e]  -> store into KK
    #pragma unroll
    for (int it = 0; it < 2; ++it) {
        int tl = tg + it*8;
        if (tl < 12) {
            int l0 = tl*4, e0 = te*4;
            float a[4][4] = {};
            #pragma unroll
            for (int dd = 0; dd < 128; ++dd) {
                float4 wf = *(float4*)&W[dd*WPAD + e0];
                float q0 = Q[(l0+0)*128+dd], q1 = Q[(l0+1)*128+dd];
                float q2 = Q[(l0+2)*128+dd], q3 = Q[(l0+3)*128+dd];
                a[0][0]+=q0*wf.x; a[0][1]+=q0*wf.y; a[0][2]+=q0*wf.z; a[0][3]+=q0*wf.w;
                a[1][0]+=q1*wf.x; a[1][1]+=q1*wf.y; a[1][2]+=q1*wf.z; a[1][3]+=q1*wf.w;
                a[2][0]+=q2*wf.x; a[2][1]+=q2*wf.y; a[2][2]+=q2*wf.z; a[2][3]+=q2*wf.w;
                a[3][0]+=q3*wf.x; a[3][1]+=q3*wf.y; a[3][2]+=q3*wf.z; a[3][3]+=q3*wf.w;
            }
            #pragma unroll
            for (int j = 0; j < 4; ++j)
                *(float4*)&KK[(l0+j)*128 + e0] = make_float4(a[j][0], a[j][1], a[j][2], a[j][3]);
        }
    }
    __syncthreads();
    // stage wo^T: W[e][c] = wo[c][e]
    for (int i = tid; i < 16384; i += 256) {
        int c = i >> 7, e = i & 127;
        W[e*WPAD + c] = wo[i];
    }
    __syncthreads();
    // enc[l][c] += sum_e att_pre[l][e] * W[e][c]
    #pragma unroll
    for (int it = 0; it < 2; ++it) {
        int tl = tg + it*8;
        if (tl < 12) {
            int l0 = tl*4, c0 = te*4;
            float a[4][4] = {};
            #pragma unroll
            for (int e = 0; e < 128; ++e) {
                float4 wf = *(float4*)&W[e*WPAD + c0];
                float t0 = KK[(l0+0)*128+e], t1 = KK[(l0+1)*128+e];
                float t2 = KK[(l0+2)*128+e], t3 = KK[(l0+3)*128+e];
                a[0][0]+=t0*wf.x; a[0][1]+=t0*wf.y; a[0][2]+=t0*wf.z; a[0][3]+=t0*wf.w;
                a[1][0]+=t1*wf.x; a[1][1]+=t1*wf.y; a[1][2]+=t1*wf.z; a[1][3]+=t1*wf.w;
                a[2][0]+=t2*wf.x; a[2][1]+=t2*wf.y; a[2][2]+=t2*wf.z; a[2][3]+=t2*wf.w;
                a[3][0]+=t3*wf.x; a[3][1]+=t3*wf.y; a[3][2]+=t3*wf.z; a[3][3]+=t3*wf.w;
            }
            #pragma unroll
            for (int j = 0; j < 4; ++j) {
                float4 cur = *(float4*)&d_enc[base + (l0+j)*128 + c0];
                cur.x += a[j][0]; cur.y += a[j][1]; cur.z += a[j][2]; cur.w += a[j][3];
                *(float4*)&d_enc[base + (l0+j)*128 + c0] = cur;
            }
        }
    }
}

// ---------------- generic SGEMM: C[m][n] = epi( sum_k A[m][k]*B[n][k] ) ----------------
// epi: 0 store, 1 +bias, 2 gelu(x+bias), 3 C += x+bias (residual in place)
__global__ void __launch_bounds__(256, 2) sgemm(
    const float* __restrict__ A, const float* __restrict__ B, float* __restrict__ C,
    int M, int N, int K, const float* __restrict__ bias, int epi)
{
    __shared__ float As[8][128];
    __shared__ float Bs[8][128];
    int m0 = blockIdx.y * 128, n0 = blockIdx.x * 128;
    int tid = threadIdx.x;
    int ar = tid >> 1, ac = (tid & 1) * 4;
    int ty = tid >> 4, tx = tid & 15;
    float acc[8][8] = {};
    for (int k0 = 0; k0 < K; k0 += 8) {
        float4 av = make_float4(0.f, 0.f, 0.f, 0.f);
        if (m0 + ar < M) av = *(const float4*)(A + (size_t)(m0 + ar)*K + k0 + ac);
        float4 bv = make_float4(0.f, 0.f, 0.f, 0.f);
        if (n0 + ar < N) bv = *(const float4*)(B + (size_t)(n0 + ar)*K + k0 + ac);
        __syncthreads();
        As[ac+0][ar] = av.x; As[ac+1][ar] = av.y; As[ac+2][ar] = av.z; As[ac+3][ar] = av.w;
        Bs[ac+0][ar] = bv.x; Bs[ac+1][ar] = bv.y; Bs[ac+2][ar] = bv.z; Bs[ac+3][ar] = bv.w;
        __syncthreads();
        #pragma unroll
        for (int k = 0; k < 8; ++k) {
            float a[8], b[8];
            *(float4*)(a)   = *(float4*)&As[k][ty*8];
            *(float4*)(a+4) = *(float4*)&As[k][ty*8+4];
            *(float4*)(b)   = *(float4*)&Bs[k][tx*8];
            *(float4*)(b+4) = *(float4*)&Bs[k][tx*8+4];
            #pragma unroll
            for (int i = 0; i < 8; ++i)
                #pragma unroll
                for (int j = 0; j < 8; ++j)
                    acc[i][j] += a[i] * b[j];
        }
    }
    #pragma unroll
    for (int i = 0; i < 8; ++i) {
        int m = m0 + ty*8 + i;
        if (m >= M) break;
        #pragma unroll
        for (int j4 = 0; j4 < 8; j4 += 4) {
            int n = n0 + tx*8 + j4;
            if (n + 3 >= N) continue;
            size_t off = (size_t)m * N + n;
            float r[4] = {acc[i][j4], acc[i][j4+1], acc[i][j4+2], acc[i][j4+3]};
            if (epi >= 1 && bias) {
                r[0] += bias[n]; r[1] += bias[n+1]; r[2] += bias[n+2]; r[3] += bias[n+3];
            }
            if (epi == 2) {
                r[0] = gelu_exact(r[0]); r[1] = gelu_exact(r[1]);
                r[2] = gelu_exact(r[2]); r[3] = gelu_exact(r[3]);
            }
            if (epi == 3) {
                float4 cur = *(float4*)(C + off);
                r[0] += cur.x; r[1] += cur.y; r[2] += cur.z; r[3] += cur.w;
            }
            *(float4*)(C + off) = make_float4(r[0], r[1], r[2], r[3]);
        }
    }
}

// ---------------- transpose enc -> X[(bl*128+d)][n] ----------------
__global__ void k_transpose() {   // grid (94, 96), 256 threads
    __shared__ float T[32*129];
    int n0 = blockIdx.x * 32;
    int bl = blockIdx.y;
    int b = bl / LL, l = bl % LL;
    int tid = threadIdx.x;
    int nrem = NN - n0; if (nrem > 32) nrem = 32;
    for (int i = tid; i < 32*128; i += 256) {
        int r = i >> 7, c = i & 127;
        if (r < nrem)
            T[r*129 + c] = d_enc[((size_t)(b*NN + n0 + r))*6144 + l*128 + c];
    }
    __syncthreads();
    for (int i = tid; i < 128*32; i += 256) {
        int dd = i >> 5, j = i & 31;
        if (j < nrem)
            d_X[((size_t)(bl*128 + dd))*NN + n0 + j] = T[j*129 + dd];
    }
}

// ---------------- per-node grouped GEMM: gout[n] = agg[n](96x128) @ pw[n](128x128) ----------------
#define GRP_SMEM ((128*WPAD + 96*128) * 4)
__global__ void __launch_bounds__(256, 1) k_grouped() {
    extern __shared__ float sm[];
    float* Wsm = sm;               // [i][o] padded WPAD
    float* Asm = sm + 128*WPAD;    // [bl][i]
    int n = blockIdx.x, tid = threadIdx.x;
    const float* pw = d_pw + (size_t)n * 16384;
    const float* ag = d_agg + (size_t)n * 12288;
    for (int i = tid; i < 16384; i += 256) {
        int ii = i >> 7, o = i & 127;
        Wsm[ii*WPAD + o] = pw[i];
    }
    for (int i = tid; i < 12288; i += 256) Asm[i] = ag[i];
    __syncthreads();
    int tc = tid & 31, tg = tid >> 5;
    #pragma unroll
    for (int it = 0; it < 3; ++it) {
        int bl0 = (tg + it*8) * 4, c0 = tc * 4;
        float a[4][4] = {};
        #pragma unroll
        for (int i = 0; i < 128; ++i) {
            float4 wf = *(float4*)&Wsm[i*WPAD + c0];
            float a0 = Asm[(bl0+0)*128+i], a1 = Asm[(bl0+1)*128+i];
            float a2 = Asm[(bl0+2)*128+i], a3 = Asm[(bl0+3)*128+i];
            a[0][0]+=a0*wf.x; a[0][1]+=a0*wf.y; a[0][2]+=a0*wf.z; a[0][3]+=a0*wf.w;
            a[1][0]+=a1*wf.x; a[1][1]+=a1*wf.y; a[1][2]+=a1*wf.z; a[1][3]+=a1*wf.w;
            a[2][0]+=a2*wf.x; a[2][1]+=a2*wf.y; a[2][2]+=a2*wf.z; a[2][3]+=a2*wf.w;
            a[3][0]+=a3*wf.x; a[3][1]+=a3*wf.y; a[3][2]+=a3*wf.z; a[3][3]+=a3*wf.w;
        }
        #pragma unroll
        for (int j = 0; j < 4; ++j)
            *(float4*)&d_gout[(size_t)n*12288 + (bl0+j)*128 + c0] =
                make_float4(a[j][0], a[j][1], a[j][2], a[j][3]);
    }
}

// ---------------- GroupNorm stats per (bl, group) ----------------
__global__ void k_gnstats() {   // grid BLL*4
    __shared__ float rs[256], rq[256];
    int bl = blockIdx.x >> 2, g = blockIdx.x & 3;
    int tid = threadIdx.x;
    float s = 0.f, q = 0.f;
    for (int i = tid; i < NN*32; i += 256) {
        int n = i >> 5, o = i & 31;
        float v = d_gout[(size_t)n*12288 + bl*128 + g*32 + o];
        s += v; q += v*v;
    }
    rs[tid] = s; rq[tid] = q;
    __syncthreads();
    for (int st = 128; st; st >>= 1) {
        if (tid < st) { rs[tid] += rs[tid+st]; rq[tid] += rq[tid+st]; }
        __syncthreads();
    }
    if (tid == 0) {
        const float inv = 1.0f / (float)(NN*32);
        float mu = rs[0] * inv;
        float var = rq[0] * inv - mu*mu;
        d_gmu[blockIdx.x] = mu;
        d_grs[blockIdx.x] = rsqrtf(var + 1e-5f);
    }
}

// ---------------- fused GN-apply + SiLU proj + time proj + mean add ----------------
__global__ void k_final(const float* __restrict__ gg, const float* __restrict__ gb,
                        const float* __restrict__ p2w, const float* __restrict__ p2b,
                        const float* __restrict__ p1w, const float* __restrict__ p1b,
                        float* __restrict__ out) {
    __shared__ float Xs[6144];
    __shared__ float Ss[LL];
    int bn = blockIdx.x;
    int b = bn / NN, n = bn % NN;
    int tid = threadIdx.x;   // 256
    for (int i = tid; i < 6144; i += 256) {
        int l = i >> 7, c = i & 127;
        int bl = b*LL + l, g = c >> 5;
        float v = d_gout[(size_t)n*12288 + bl*128 + c];
        Xs[i] = (v - d_gmu[bl*4+g]) * d_grs[bl*4+g] * gg[c] + gb[c];
    }
    __syncthreads();
    int lane = tid & 31, w = tid >> 5;
    for (int l = w*6; l < w*6+6; ++l) {
        float s = Xs[l*128+lane]*p2w[lane] + Xs[l*128+lane+32]*p2w[lane+32]
                + Xs[l*128+lane+64]*p2w[lane+64] + Xs[l*128+lane+96]*p2w[lane+96];
        #pragma unroll
        for (int o = 16; o; o >>= 1) s += __shfl_xor_sync(~0u, s, o);
        if (lane == 0) {
            float z = s + p2b[0];
            Ss[l] = z / (1.0f + expf(-z));
        }
    }
    __syncthreads();
    if (tid < L_OUT) {
        float acc = p1b[tid];
        #pragma unroll
        for (int l = 0; l < LL; ++l) acc += Ss[l] * p1w[tid*LL + l];
        out[((size_t)(b*L_OUT + tid))*NN + n] = acc + d_mean[bn];
    }
}

// ---------------- launcher ----------------
extern "C" void kernel_launch(void* const* d_in, const int* in_sizes, int n_in,
                              void* d_out, int out_size) {
    const float* x_enc   = (const float*)d_in[0];
    const float* adj     = (const float*)d_in[1];
    const float* pe_raw  = (const float*)d_in[2];
    const float* conv_w  = (const float*)d_in[3];
    const float* pos_w   = (const float*)d_in[4];
    const float* pos_b   = (const float*)d_in[5];
    const float* wq      = (const float*)d_in[6];
    const float* wk      = (const float*)d_in[7];
    const float* wv      = (const float*)d_in[8];
    const float* wo      = (const float*)d_in[9];
    const float* ln1_g   = (const float*)d_in[10];
    const float* ln1_b   = (const float*)d_in[11];
    const float* ff_w1   = (const float*)d_in[12];
    const float* ff_b1   = (const float*)d_in[13];
    const float* ff_w2   = (const float*)d_in[14];
    const float* ff_b2   = (const float*)d_in[15];
    const float* ln2_g   = (const float*)d_in[16];
    const float* ln2_b   = (const float*)d_in[17];
    const float* wpool   = (const float*)d_in[18];
    const float* gn_g    = (const float*)d_in[19];
    const float* gn_b    = (const float*)d_in[20];
    const float* p2_w    = (const float*)d_in[21];
    const float* p2_b    = (const float*)d_in[22];
    const float* p1_w    = (const float*)d_in[23];
    const float* p1_b    = (const float*)d_in[24];
    float* out = (float*)d_out;

    float *p_enc, *p_h, *p_q, *p_k, *p_v, *p_ff, *p_X, *p_agg, *p_pe2, *p_pw, *p_peT, *p_WT2;
    cudaGetSymbolAddress((void**)&p_enc, d_enc);
    cudaGetSymbolAddress((void**)&p_h,   d_h);
    cudaGetSymbolAddress((void**)&p_q,   d_qb);
    cudaGetSymbolAddress((void**)&p_k,   d_kb);
    cudaGetSymbolAddress((void**)&p_v,   d_vb);
    cudaGetSymbolAddress((void**)&p_ff,  d_ff);
    cudaGetSymbolAddress((void**)&p_X,   d_X);
    cudaGetSymbolAddress((void**)&p_agg, d_agg);
    cudaGetSymbolAddress((void**)&p_pe2, d_pe2);
    cudaGetSymbolAddress((void**)&p_pw,  d_pw);
    cudaGetSymbolAddress((void**)&p_peT, d_peT);
    cudaGetSymbolAddress((void**)&p_WT2, d_WT2);

    cudaFuncSetAttribute(k_attn,    cudaFuncAttributeMaxDynamicSharedMemorySize, ATTN_SMEM);
    cudaFuncSetAttribute(k_grouped, cudaFuncAttributeMaxDynamicSharedMemorySize, GRP_SMEM);

    // prep
    k_mean<<<(BNN+255)/256, 256>>>(x_enc);
    k_peT<<<(DD*NN+255)/256, 256>>>(pe_raw, pos_w, pos_b);
    k_WT2<<<(DD*DD*DD+255)/256, 256>>>(wpool);
    k_conv<<<BNN, 128>>>(x_enc, conv_w);

    // temporal transformer
    k_ln<<<ROWS/8, 256>>>(p_enc, p_h, ln1_g, ln1_b);
    sgemm<<<dim3(1, ROWS/128), 256>>>(p_h, wq, p_q, ROWS, 128, 128, nullptr, 0);
    sgemm<<<dim3(1, ROWS/128), 256>>>(p_h, wk, p_k, ROWS, 128, 128, nullptr, 0);
    sgemm<<<dim3(1, ROWS/128), 256>>>(p_h, wv, p_v, ROWS, 128, 128, nullptr, 0);
    k_smax_row<<<ROWS/8, 256>>>(p_q, 0.08838834764831845f);   // d^-0.5
    k_smax_col<<<BNN, 128>>>(p_k);
    k_attn<<<BNN, 256, ATTN_SMEM>>>(wo);
    k_ln<<<ROWS/8, 256>>>(p_enc, p_h, ln2_g, ln2_b);
    sgemm<<<dim3(4, ROWS/128), 256>>>(p_h, ff_w1, p_ff, ROWS, 512, 128, ff_b1, 2);
    sgemm<<<dim3(1, ROWS/128), 256>>>(p_ff, ff_w2, p_enc, ROWS, 128, 512, ff_b2, 3);

    // spatial GCN
    k_transpose<<<dim3(94, BLL), 256>>>();
    sgemm<<<dim3(1,  24), 256>>>(adj,   p_peT, p_pe2, NN, 128,   NN,  nullptr, 0);
    sgemm<<<dim3(128,24), 256>>>(p_pe2, p_WT2, p_pw,  NN, 16384, 128, nullptr, 0);
    sgemm<<<dim3(96, 24), 256>>>(adj,   p_X,   p_agg, NN, 12288, NN,  nullptr, 0);
    k_grouped<<<NN, 256, GRP_SMEM>>>();

    // groupnorm + head
    k_gnstats<<<BLL*4, 256>>>();
    k_final<<<BNN, 256>>>(gn_g, gn_b, p2_w, p2_b, p1_w, p1_b, out);
}

// round 3
// speedup vs baseline: 1.2498x; 1.2498x over previous
#include <cuda_runtime.h>
#include <math.h>
#include <stdint.h>

#define BB 2
#define LL 48
#define NN 3000
#define DD 128
#define L_OUT 24
#define BNN (BB*NN)          // 6000
#define BLL (BB*LL)          // 96
#define ROWS (BNN*LL)        // 288000 token rows
#define ENC_N (ROWS*DD)      // 36,864,000

// ---------------- scratch (device globals; no runtime allocation) ----------------
__device__ float d_mean[BNN];
__device__ float d_peT[DD*NN];           // peT[d][n]
__device__ float d_WT2[DD*DD*DD];        // WT2[(i*128+o)][d] = wp[d][i][o]
__device__ float d_pe2[NN*DD];           // pe2[n][d]
__device__ float d_enc[ENC_N];           // enc[seq][l][c], seq = b*NN+n
__device__ float d_h[ENC_N];             // LN output (reused for LN2)
__device__ float d_qb[ENC_N];            // q, later att_pre
__device__ float d_kb[ENC_N];
__device__ float d_vb[ENC_N];
__device__ float d_ff[ROWS*512];         // gelu intermediate
__device__ float d_X[BLL*DD*NN];         // X[(bl*128+d)][n] = enc[(b,n)][l][d]
__device__ float d_agg[NN*BLL*DD];       // agg[n][bl][i]
__device__ float d_pw[NN*DD*DD];         // pw[n][i][o]
__device__ float d_gout[NN*BLL*DD];      // gout[n][bl][o]
__device__ float d_gmu[BLL*4];
__device__ float d_grs[BLL*4];

__device__ __forceinline__ float gelu_exact(float x) {
    return 0.5f * x * (1.0f + erff(x * 0.70710678118654752f));
}
__device__ __forceinline__ float to_tf32(float x) {
    float r;
    asm("cvt.rna.tf32.f32 %0, %1;" : "=f"(r) : "f"(x));
    return r;
}
__device__ __forceinline__ void split_tf32(float v, uint32_t& hi, uint32_t& lo) {
    float h = to_tf32(v);
    float l = to_tf32(v - h);
    hi = __float_as_uint(h);
    lo = __float_as_uint(l);
}

// ---------------- small prep kernels ----------------
__global__ void k_mean(const float* __restrict__ x) {
    int i = blockIdx.x * blockDim.x + threadIdx.x;
    if (i >= BNN) return;
    int b = i / NN, n = i % NN;
    float s = 0.f;
    #pragma unroll
    for (int l = 0; l < LL; ++l) s += x[(b*LL + l)*NN + n];
    d_mean[i] = s * (1.0f / LL);
}

__global__ void k_peT(const float* __restrict__ pr, const float* __restrict__ pw,
                      const float* __restrict__ pb) {
    int i = blockIdx.x * blockDim.x + threadIdx.x;
    if (i >= DD*NN) return;
    int d = i / NN, n = i % NN;
    d_peT[i] = pr[n]*pw[d*3] + pr[NN+n]*pw[d*3+1] + pr[2*NN+n]*pw[d*3+2] + pb[d];
}

__global__ void k_WT2(const float* __restrict__ wp) {
    int idx = blockIdx.x * blockDim.x + threadIdx.x;
    if (idx >= DD*DD*DD) return;
    int d = idx & 127;
    int io = idx >> 7;
    int o = io & 127, ii = io >> 7;
    d_WT2[idx] = wp[(d*128 + ii)*128 + o];
}

// circular conv1d k=3: enc[seq][l][c]
__global__ void k_conv(const float* __restrict__ x, const float* __restrict__ cw) {
    __shared__ float xs[LL + 2];
    int seq = blockIdx.x;
    int b = seq / NN, n = seq % NN;
    float m = d_mean[seq];
    int t = threadIdx.x;   // 128
    if (t < LL) xs[t + 1] = x[(b*LL + t)*NN + n] - m;
    __syncthreads();
    if (t == 0) { xs[0] = xs[LL]; xs[LL+1] = xs[1]; }
    __syncthreads();
    float w0 = cw[t*3], w1 = cw[t*3+1], w2 = cw[t*3+2];
    float* out = d_enc + (size_t)seq * (LL*DD);
    #pragma unroll
    for (int l = 0; l < LL; ++l)
        out[l*DD + t] = w0*xs[l] + w1*xs[l+1] + w2*xs[l+2];
}

// LayerNorm over rows of 128 (one warp per row)
__global__ void k_ln(const float* __restrict__ X, float* __restrict__ Y,
                     const float* __restrict__ g, const float* __restrict__ bta) {
    int warp = (blockIdx.x * blockDim.x + threadIdx.x) >> 5;
    int lane = threadIdx.x & 31;
    const float* xr = X + (size_t)warp * DD;
    float4 v = *(const float4*)(xr + lane*4);
    float s = v.x + v.y + v.z + v.w;
    float sq = v.x*v.x + v.y*v.y + v.z*v.z + v.w*v.w;
    #pragma unroll
    for (int o = 16; o; o >>= 1) {
        s  += __shfl_xor_sync(~0u, s, o);
        sq += __shfl_xor_sync(~0u, sq, o);
    }
    float mu = s * (1.0f/DD);
    float var = sq * (1.0f/DD) - mu*mu;
    float rs = rsqrtf(var + 1e-5f);
    float4 gg = *(const float4*)(g + lane*4);
    float4 bb = *(const float4*)(bta + lane*4);
    float4 o4;
    o4.x = (v.x - mu)*rs*gg.x + bb.x;
    o4.y = (v.y - mu)*rs*gg.y + bb.y;
    o4.z = (v.z - mu)*rs*gg.z + bb.z;
    o4.w = (v.w - mu)*rs*gg.w + bb.w;
    *(float4*)(Y + (size_t)warp*DD + lane*4) = o4;
}

// softmax over feature dim (rows of 128), then * sc
__global__ void k_smax_row(float* __restrict__ X, float sc) {
    int warp = (blockIdx.x * blockDim.x + threadIdx.x) >> 5;
    int lane = threadIdx.x & 31;
    float* xr = X + (size_t)warp * DD;
    float4 v = *(float4*)(xr + lane*4);
    float mx = fmaxf(fmaxf(v.x, v.y), fmaxf(v.z, v.w));
    #pragma unroll
    for (int o = 16; o; o >>= 1) mx = fmaxf(mx, __shfl_xor_sync(~0u, mx, o));
    v.x = expf(v.x - mx); v.y = expf(v.y - mx);
    v.z = expf(v.z - mx); v.w = expf(v.w - mx);
    float s = v.x + v.y + v.z + v.w;
    #pragma unroll
    for (int o = 16; o; o >>= 1) s += __shfl_xor_sync(~0u, s, o);
    float f = sc / s;
    v.x *= f; v.y *= f; v.z *= f; v.w *= f;
    *(float4*)(xr + lane*4) = v;
}

// softmax over L (axis=1) per (seq, feature)
__global__ void k_smax_col(float* __restrict__ X) {
    int seq = blockIdx.x;
    int c = threadIdx.x;     // 128
    float* p = X + (size_t)seq * (LL*DD) + c;
    float v[LL];
    float mx = -1e30f;
    #pragma unroll
    for (int l = 0; l < LL; ++l) { v[l] = p[l*DD]; mx = fmaxf(mx, v[l]); }
    float s = 0.f;
    #pragma unroll
    for (int l = 0; l < LL; ++l) { v[l] = expf(v[l] - mx); s += v[l]; }
    float inv = 1.0f / s;
    #pragma unroll
    for (int l = 0; l < LL; ++l) p[l*DD] = v[l] * inv;
}

// ---------------- per-sequence linear attention (ctx + q@ctx only) ----------------
// ctx = kk^T @ v ; att_pre = q @ ctx  -> written to d_qb (wo projection is a big GEMM)
#define WPAD 132
#define ATTN_SMEM ((6144*3 + 128*WPAD) * 4)
__global__ void __launch_bounds__(256, 1) k_attn() {
    extern __shared__ float sm[];
    float* Q  = sm;
    float* KK = sm + 6144;
    float* V  = sm + 12288;
    float* W  = sm + 18432;    // ctx 128 x WPAD
    int seq = blockIdx.x, tid = threadIdx.x;
    size_t base = (size_t)seq * 6144;
    for (int i = tid; i < 6144; i += 256) {
        Q[i] = d_qb[base+i]; KK[i] = d_kb[base+i]; V[i] = d_vb[base+i];
    }
    __syncthreads();
    int te = tid & 31, tg = tid >> 5;
    // ctx[dd][e] = sum_l KK[l][dd]*V[l][e]
    #pragma unroll
    for (int it = 0; it < 4; ++it) {
        int dd0 = (tg + it*8) * 4, e0 = te * 4;
        float a[4][4] = {};
        #pragma unroll
        for (int l = 0; l < LL; ++l) {
            float4 kf = *(float4*)&KK[l*128 + dd0];
            float4 vf = *(float4*)&V[l*128 + e0];
            a[0][0]+=kf.x*vf.x; a[0][1]+=kf.x*vf.y; a[0][2]+=kf.x*vf.z; a[0][3]+=kf.x*vf.w;
            a[1][0]+=kf.y*vf.x; a[1][1]+=kf.y*vf.y; a[1][2]+=kf.y*vf.z; a[1][3]+=kf.y*vf.w;
            a[2][0]+=kf.z*vf.x; a[2][1]+=kf.z*vf.y; a[2][2]+=kf.z*vf.z; a[2][3]+=kf.z*vf.w;
            a[3][0]+=kf.w*vf.x; a[3][1]+=kf.w*vf.y; a[3][2]+=kf.w*vf.z; a[3][3]+=kf.w*vf.w;
        }
        #pragma unroll
        for (int j = 0; j < 4; ++j)
            *(float4*)&W[(dd0+j)*WPAD + e0] = make_float4(a[j][0], a[j][1], a[j][2], a[j][3]);
    }
    __syncthreads();
    // att_pre[l][e] = sum_dd Q[l][dd]*ctx[dd][e] -> write to d_qb
    #pragma unroll
    for (int it = 0; it < 2; ++it) {
        int tl = tg + it*8;
        if (tl < 12) {
            int l0 = tl*4, e0 = te*4;
            float a[4][4] = {};
            #pragma unroll
            for (int dd = 0; dd < 128; ++dd) {
                float4 wf = *(float4*)&W[dd*WPAD + e0];
                float q0 = Q[(l0+0)*128+dd], q1 = Q[(l0+1)*128+dd];
                float q2 = Q[(l0+2)*128+dd], q3 = Q[(l0+3)*128+dd];
                a[0][0]+=q0*wf.x; a[0][1]+=q0*wf.y; a[0][2]+=q0*wf.z; a[0][3]+=q0*wf.w;
                a[1][0]+=q1*wf.x; a[1][1]+=q1*wf.y; a[1][2]+=q1*wf.z; a[1][3]+=q1*wf.w;
                a[2][0]+=q2*wf.x; a[2][1]+=q2*wf.y; a[2][2]+=q2*wf.z; a[2][3]+=q2*wf.w;
                a[3][0]+=q3*wf.x; a[3][1]+=q3*wf.y; a[3][2]+=q3*wf.z; a[3][3]+=q3*wf.w;
            }
            #pragma unroll
            for (int j = 0; j < 4; ++j)
                *(float4*)&d_qb[base + (l0+j)*128 + e0] =
                    make_float4(a[j][0], a[j][1], a[j][2], a[j][3]);
        }
    }
}

// ---------------- 3xTF32 tensor-core GEMM: C[m][n] = epi( sum_k A[m][k]*B[n][k] ) ----------------
// fp32 in smem; hi/lo tf32 split at fragment load. acc += ah*bh + ah*bl + al*bh.
// epi: 0 store, 2 gelu(x+bias), 3 C += x (+bias)
#define TGK 16
#define TGP 20   // padded k-stride
__global__ void __launch_bounds__(256) tgemm(
    const float* __restrict__ A, const float* __restrict__ B, float* __restrict__ C,
    int M, int N, int K, const float* __restrict__ bias, int epi)
{
    __shared__ float As[2][128][TGP];
    __shared__ float Bs[2][128][TGP];
    int tid = threadIdx.x;
    int m0 = blockIdx.y * 128, n0 = blockIdx.x * 128;
    int lrow = tid >> 1;            // 0..127
    int lk   = (tid & 1) * 8;       // 0 or 8
    int warp = tid >> 5, lane = tid & 31;
    int wm = (warp >> 2) * 64, wn = (warp & 3) * 32;
    int g = lane >> 2, tig = lane & 3;

    float acc[4][4][4];
    #pragma unroll
    for (int a = 0; a < 4; ++a)
        #pragma unroll
        for (int b = 0; b < 4; ++b)
            #pragma unroll
            for (int c = 0; c < 4; ++c) acc[a][b][c] = 0.f;

    int nk = (K + TGK - 1) / TGK;
    const float* Arow = A + (size_t)(m0 + lrow) * K;
    const float* Brow = B + (size_t)(n0 + lrow) * K;
    bool mok = (m0 + lrow) < M;
    bool nok = (n0 + lrow) < N;

    float ra[8], rb[8];
    {
        int k = lk;
        #pragma unroll
        for (int j = 0; j < 8; j += 4) {
            float4 av = make_float4(0,0,0,0), bv = make_float4(0,0,0,0);
            if (mok && (k + j) < K) av = *(const float4*)(Arow + k + j);
            if (nok && (k + j) < K) bv = *(const float4*)(Brow + k + j);
            ra[j]=av.x; ra[j+1]=av.y; ra[j+2]=av.z; ra[j+3]=av.w;
            rb[j]=bv.x; rb[j+1]=bv.y; rb[j+2]=bv.z; rb[j+3]=bv.w;
        }
        #pragma unroll
        for (int j = 0; j < 8; ++j) {
            As[0][lrow][lk+j] = ra[j];
            Bs[0][lrow][lk+j] = rb[j];
        }
    }
    __syncthreads();

    int s = 0;
    for (int kt = 0; kt < nk; ++kt) {
        bool nxt = (kt + 1) < nk;
        if (nxt) {
            int k = (kt + 1) * TGK + lk;
            #pragma unroll
            for (int j = 0; j < 8; j += 4) {
                float4 av = make_float4(0,0,0,0), bv = make_float4(0,0,0,0);
                if (mok && (k + j) < K) av = *(const float4*)(Arow + k + j);
                if (nok && (k + j) < K) bv = *(const float4*)(Brow + k + j);
                ra[j]=av.x; ra[j+1]=av.y; ra[j+2]=av.z; ra[j+3]=av.w;
                rb[j]=bv.x; rb[j+1]=bv.y; rb[j+2]=bv.z; rb[j+3]=bv.w;
            }
        }
        #pragma unroll
        for (int ks = 0; ks < TGK; ks += 8) {
            uint32_t ah[4][4], al[4][4], bh[4][2], bl[4][2];
            #pragma unroll
            for (int mi = 0; mi < 4; ++mi) {
                int r = wm + mi*16 + g;
                split_tf32(As[s][r  ][ks+tig  ], ah[mi][0], al[mi][0]);
                split_tf32(As[s][r+8][ks+tig  ], ah[mi][1], al[mi][1]);
                split_tf32(As[s][r  ][ks+tig+4], ah[mi][2], al[mi][2]);
                split_tf32(As[s][r+8][ks+tig+4], ah[mi][3], al[mi][3]);
            }
            #pragma unroll
            for (int ni = 0; ni < 4; ++ni) {
                int r = wn + ni*8 + g;
                split_tf32(Bs[s][r][ks+tig  ], bh[ni][0], bl[ni][0]);
                split_tf32(Bs[s][r][ks+tig+4], bh[ni][1], bl[ni][1]);
            }
            #pragma unroll
            for (int mi = 0; mi < 4; ++mi)
                #pragma unroll
                for (int ni = 0; ni < 4; ++ni) {
                    asm volatile(
                        "mma.sync.aligned.m16n8k8.row.col.f32.tf32.tf32.f32 "
                        "{%0,%1,%2,%3}, {%4,%5,%6,%7}, {%8,%9}, {%0,%1,%2,%3};"
                        : "+f"(acc[mi][ni][0]), "+f"(acc[mi][ni][1]),
                          "+f"(acc[mi][ni][2]), "+f"(acc[mi][ni][3])
                        : "r"(ah[mi][0]), "r"(ah[mi][1]), "r"(ah[mi][2]), "r"(ah[mi][3]),
                          "r"(bl[ni][0]), "r"(bl[ni][1]));
                    asm volatile(
                        "mma.sync.aligned.m16n8k8.row.col.f32.tf32.tf32.f32 "
                        "{%0,%1,%2,%3}, {%4,%5,%6,%7}, {%8,%9}, {%0,%1,%2,%3};"
                        : "+f"(acc[mi][ni][0]), "+f"(acc[mi][ni][1]),
                          "+f"(acc[mi][ni][2]), "+f"(acc[mi][ni][3])
                        : "r"(al[mi][0]), "r"(al[mi][1]), "r"(al[mi][2]), "r"(al[mi][3]),
                          "r"(bh[ni][0]), "r"(bh[ni][1]));
                    asm volatile(
                        "mma.sync.aligned.m16n8k8.row.col.f32.tf32.tf32.f32 "
                        "{%0,%1,%2,%3}, {%4,%5,%6,%7}, {%8,%9}, {%0,%1,%2,%3};"
                        : "+f"(acc[mi][ni][0]), "+f"(acc[mi][ni][1]),
                          "+f"(acc[mi][ni][2]), "+f"(acc[mi][ni][3])
                        : "r"(ah[mi][0]), "r"(ah[mi][1]), "r"(ah[mi][2]), "r"(ah[mi][3]),
                          "r"(bh[ni][0]), "r"(bh[ni][1]));
                }
        }
        if (nxt) {
            #pragma unroll
            for (int j = 0; j < 8; ++j) {
                As[s^1][lrow][lk+j] = ra[j];
                Bs[s^1][lrow][lk+j] = rb[j];
            }
        }
        __syncthreads();
        s ^= 1;
    }

    // epilogue
    #pragma unroll
    for (int mi = 0; mi < 4; ++mi) {
        #pragma unroll
        for (int ni = 0; ni < 4; ++ni) {
            int n = n0 + wn + ni*8 + tig*2;
            float bv0 = 0.f, bv1 = 0.f;
            if (bias) { bv0 = bias[n]; bv1 = bias[n+1]; }
            #pragma unroll
            for (int half = 0; half < 2; ++half) {
                int m = m0 + wm + mi*16 + g + half*8;
                if (m >= M) continue;
                float r0 = acc[mi][ni][half*2+0] + bv0;
                float r1 = acc[mi][ni][half*2+1] + bv1;
                size_t off = (size_t)m * N + n;
                if (epi == 2) { r0 = gelu_exact(r0); r1 = gelu_exact(r1); }
                if (epi == 3) {
                    float2 cur = *(float2*)(C + off);
                    r0 += cur.x; r1 += cur.y;
                }
                *(float2*)(C + off) = make_float2(r0, r1);
            }
        }
    }
}

// ---------------- transpose enc -> X[(bl*128+d)][n] ----------------
__global__ void k_transpose() {   // grid (94, 96), 256 threads
    __shared__ float T[32*129];
    int n0 = blockIdx.x * 32;
    int bl = blockIdx.y;
    int b = bl / LL, l = bl % LL;
    int tid = threadIdx.x;
    int nrem = NN - n0; if (nrem > 32) nrem = 32;
    for (int i = tid; i < 32*128; i += 256) {
        int r = i >> 7, c = i & 127;
        if (r < nrem)
            T[r*129 + c] = d_enc[((size_t)(b*NN + n0 + r))*6144 + l*128 + c];
    }
    __syncthreads();
    for (int i = tid; i < 128*32; i += 256) {
        int dd = i >> 5, j = i & 31;
        if (j < nrem)
            d_X[((size_t)(bl*128 + dd))*NN + n0 + j] = T[j*129 + dd];
    }
}

// ---------------- per-node grouped GEMM: gout[n] = agg[n](96x128) @ pw[n](128x128) ----------------
#define GRP_SMEM ((128*WPAD + 96*128) * 4)
__global__ void __launch_bounds__(256, 1) k_grouped() {
    extern __shared__ float sm[];
    float* Wsm = sm;               // [i][o] padded WPAD
    float* Asm = sm + 128*WPAD;    // [bl][i]
    int n = blockIdx.x, tid = threadIdx.x;
    const float* pw = d_pw + (size_t)n * 16384;
    const float* ag = d_agg + (size_t)n * 12288;
    for (int i = tid; i < 16384; i += 256) {
        int ii = i >> 7, o = i & 127;
        Wsm[ii*WPAD + o] = pw[i];
    }
    for (int i = tid; i < 12288; i += 256) Asm[i] = ag[i];
    __syncthreads();
    int tc = tid & 31, tg = tid >> 5;
    #pragma unroll
    for (int it = 0; it < 3; ++it) {
        int bl0 = (tg + it*8) * 4, c0 = tc * 4;
        float a[4][4] = {};
        #pragma unroll
        for (int i = 0; i < 128; ++i) {
            float4 wf = *(float4*)&Wsm[i*WPAD + c0];
            float a0 = Asm[(bl0+0)*128+i], a1 = Asm[(bl0+1)*128+i];
            float a2 = Asm[(bl0+2)*128+i], a3 = Asm[(bl0+3)*128+i];
            a[0][0]+=a0*wf.x; a[0][1]+=a0*wf.y; a[0][2]+=a0*wf.z; a[0][3]+=a0*wf.w;
            a[1][0]+=a1*wf.x; a[1][1]+=a1*wf.y; a[1][2]+=a1*wf.z; a[1][3]+=a1*wf.w;
            a[2][0]+=a2*wf.x; a[2][1]+=a2*wf.y; a[2][2]+=a2*wf.z; a[2][3]+=a2*wf.w;
            a[3][0]+=a3*wf.x; a[3][1]+=a3*wf.y; a[3][2]+=a3*wf.z; a[3][3]+=a3*wf.w;
        }
        #pragma unroll
        for (int j = 0; j < 4; ++j)
            *(float4*)&d_gout[(size_t)n*12288 + (bl0+j)*128 + c0] =
                make_float4(a[j][0], a[j][1], a[j][2], a[j][3]);
    }
}

// ---------------- GroupNorm stats per (bl, group) ----------------
__global__ void k_gnstats() {   // grid BLL*4
    __shared__ float rs[256], rq[256];
    int bl = blockIdx.x >> 2, g = blockIdx.x & 3;
    int tid = threadIdx.x;
    float s = 0.f, q = 0.f;
    for (int i = tid; i < NN*32; i += 256) {
        int n = i >> 5, o = i & 31;
        float v = d_gout[(size_t)n*12288 + bl*128 + g*32 + o];
        s += v; q += v*v;
    }
    rs[tid] = s; rq[tid] = q;
    __syncthreads();
    for (int st = 128; st; st >>= 1) {
        if (tid < st) { rs[tid] += rs[tid+st]; rq[tid] += rq[tid+st]; }
        __syncthreads();
    }
    if (tid == 0) {
        const float inv = 1.0f / (float)(NN*32);
        float mu = rs[0] * inv;
        float var = rq[0] * inv - mu*mu;
        d_gmu[blockIdx.x] = mu;
        d_grs[blockIdx.x] = rsqrtf(var + 1e-5f);
    }
}

// ---------------- fused GN-apply + SiLU proj + time proj + mean add ----------------
__global__ void k_final(const float* __restrict__ gg, const float* __restrict__ gb,
                        const float* __restrict__ p2w, const float* __restrict__ p2b,
                        const float* __restrict__ p1w, const float* __restrict__ p1b,
                        float* __restrict__ out) {
    __shared__ float Xs[6144];
    __shared__ float Ss[LL];
    int bn = blockIdx.x;
    int b = bn / NN, n = bn % NN;
    int tid = threadIdx.x;   // 256
    for (int i = tid; i < 6144; i += 256) {
        int l = i >> 7, c = i & 127;
        int bl = b*LL + l, g = c >> 5;
        float v = d_gout[(size_t)n*12288 + bl*128 + c];
        Xs[i] = (v - d_gmu[bl*4+g]) * d_grs[bl*4+g] * gg[c] + gb[c];
    }
    __syncthreads();
    int lane = tid & 31, w = tid >> 5;
    for (int l = w*6; l < w*6+6; ++l) {
        float s = Xs[l*128+lane]*p2w[lane] + Xs[l*128+lane+32]*p2w[lane+32]
                + Xs[l*128+lane+64]*p2w[lane+64] + Xs[l*128+lane+96]*p2w[lane+96];
        #pragma unroll
        for (int o = 16; o; o >>= 1) s += __shfl_xor_sync(~0u, s, o);
        if (lane == 0) {
            float z = s + p2b[0];
            Ss[l] = z / (1.0f + expf(-z));
        }
    }
    __syncthreads();
    if (tid < L_OUT) {
        float acc = p1b[tid];
        #pragma unroll
        for (int l = 0; l < LL; ++l) acc += Ss[l] * p1w[tid*LL + l];
        out[((size_t)(b*L_OUT + tid))*NN + n] = acc + d_mean[bn];
    }
}

// ---------------- launcher ----------------
extern "C" void kernel_launch(void* const* d_in, const int* in_sizes, int n_in,
                              void* d_out, int out_size) {
    const float* x_enc   = (const float*)d_in[0];
    const float* adj     = (const float*)d_in[1];
    const float* pe_raw  = (const float*)d_in[2];
    const float* conv_w  = (const float*)d_in[3];
    const float* pos_w   = (const float*)d_in[4];
    const float* pos_b   = (const float*)d_in[5];
    const float* wq      = (const float*)d_in[6];
    const float* wk      = (const float*)d_in[7];
    const float* wv      = (const float*)d_in[8];
    const float* wo      = (const float*)d_in[9];
    const float* ln1_g   = (const float*)d_in[10];
    const float* ln1_b   = (const float*)d_in[11];
    const float* ff_w1   = (const float*)d_in[12];
    const float* ff_b1   = (const float*)d_in[13];
    const float* ff_w2   = (const float*)d_in[14];
    const float* ff_b2   = (const float*)d_in[15];
    const float* ln2_g   = (const float*)d_in[16];
    const float* ln2_b   = (const float*)d_in[17];
    const float* wpool   = (const float*)d_in[18];
    const float* gn_g    = (const float*)d_in[19];
    const float* gn_b    = (const float*)d_in[20];
    const float* p2_w    = (const float*)d_in[21];
    const float* p2_b    = (const float*)d_in[22];
    const float* p1_w    = (const float*)d_in[23];
    const float* p1_b    = (const float*)d_in[24];
    float* out = (float*)d_out;

    float *p_enc, *p_h, *p_q, *p_k, *p_v, *p_ff, *p_X, *p_agg, *p_pe2, *p_pw, *p_peT, *p_WT2;
    cudaGetSymbolAddress((void**)&p_enc, d_enc);
    cudaGetSymbolAddress((void**)&p_h,   d_h);
    cudaGetSymbolAddress((void**)&p_q,   d_qb);
    cudaGetSymbolAddress((void**)&p_k,   d_kb);
    cudaGetSymbolAddress((void**)&p_v,   d_vb);
    cudaGetSymbolAddress((void**)&p_ff,  d_ff);
    cudaGetSymbolAddress((void**)&p_X,   d_X);
    cudaGetSymbolAddress((void**)&p_agg, d_agg);
    cudaGetSymbolAddress((void**)&p_pe2, d_pe2);
    cudaGetSymbolAddress((void**)&p_pw,  d_pw);
    cudaGetSymbolAddress((void**)&p_peT, d_peT);
    cudaGetSymbolAddress((void**)&p_WT2, d_WT2);

    cudaFuncSetAttribute(k_attn,    cudaFuncAttributeMaxDynamicSharedMemorySize, ATTN_SMEM);
    cudaFuncSetAttribute(k_grouped, cudaFuncAttributeMaxDynamicSharedMemorySize, GRP_SMEM);

    // prep
    k_mean<<<(BNN+255)/256, 256>>>(x_enc);
    k_peT<<<(DD*NN+255)/256, 256>>>(pe_raw, pos_w, pos_b);
    k_WT2<<<(DD*DD*DD+255)/256, 256>>>(wpool);
    k_conv<<<BNN, 128>>>(x_enc, conv_w);

    // temporal transformer
    k_ln<<<ROWS/8, 256>>>(p_enc, p_h, ln1_g, ln1_b);
    tgemm<<<dim3(1, ROWS/128), 256>>>(p_h, wq, p_q, ROWS, 128, 128, nullptr, 0);
    tgemm<<<dim3(1, ROWS/128), 256>>>(p_h, wk, p_k, ROWS, 128, 128, nullptr, 0);
    tgemm<<<dim3(1, ROWS/128), 256>>>(p_h, wv, p_v, ROWS, 128, 128, nullptr, 0);
    k_smax_row<<<ROWS/8, 256>>>(p_q, 0.08838834764831845f);   // d^-0.5
    k_smax_col<<<BNN, 128>>>(p_k);
    k_attn<<<BNN, 256, ATTN_SMEM>>>();
    tgemm<<<dim3(1, ROWS/128), 256>>>(p_q, wo, p_enc, ROWS, 128, 128, nullptr, 3);  // enc += att@wo^T
    k_ln<<<ROWS/8, 256>>>(p_enc, p_h, ln2_g, ln2_b);
    tgemm<<<dim3(4, ROWS/128), 256>>>(p_h, ff_w1, p_ff, ROWS, 512, 128, ff_b1, 2);
    tgemm<<<dim3(1, ROWS/128), 256>>>(p_ff, ff_w2, p_enc, ROWS, 128, 512, ff_b2, 3);

    // spatial GCN
    k_transpose<<<dim3(94, BLL), 256>>>();
    tgemm<<<dim3(1,   24), 256>>>(adj,   p_peT, p_pe2, NN, 128,   NN,  nullptr, 0);
    tgemm<<<dim3(128, 24), 256>>>(p_pe2, p_WT2, p_pw,  NN, 16384, 128, nullptr, 0);
    tgemm<<<dim3(96,  24), 256>>>(adj,   p_X,   p_agg, NN, 12288, NN,  nullptr, 0);
    k_grouped<<<NN, 256, GRP_SMEM>>>();

    // groupnorm + head
    k_gnstats<<<BLL*4, 256>>>();
    k_final<<<BNN, 256>>>(gn_g, gn_b, p2_w, p2_b, p1_w, p1_b, out);
}

// round 4
// speedup vs baseline: 1.6482x; 1.3188x over previous
#include <cuda_runtime.h>
#include <math.h>
#include <stdint.h>

#define BB 2
#define LL 48
#define NN 3000
#define DD 128
#define L_OUT 24
#define BNN (BB*NN)          // 6000
#define BLL (BB*LL)          // 96
#define ROWS (BNN*LL)        // 288000 token rows
#define ENC_N (ROWS*DD)      // 36,864,000

// ---------------- scratch (device globals; no runtime allocation) ----------------
__device__ float d_mean[BNN];
__device__ float d_peT[DD*NN];           // peT[d][n]
__device__ float d_WT2[DD*DD*DD];        // WT2[(i*128+o)][d] = wp[d][i][o]
__device__ float d_pe2[NN*DD];           // pe2[n][d]
__device__ float d_enc[ENC_N];           // enc[seq][l][c], seq = b*NN+n
__device__ float d_h[ENC_N];             // LN output (reused for LN2)
__device__ float d_qb[ENC_N];            // q raw, later att_pre
__device__ float d_kb[ENC_N];
__device__ float d_vb[ENC_N];
__device__ float d_ff[ROWS*512];         // gelu intermediate
__device__ float d_X[BLL*DD*NN];         // X[(bl*128+d)][n] = enc[(b,n)][l][d]
__device__ float d_agg[NN*BLL*DD];       // agg[n][bl][i]
__device__ float d_pw[NN*DD*DD];         // pw[n][i][o]
__device__ float d_gout[NN*BLL*DD];      // gout[n][bl][o]
__device__ float d_gmu[BLL*4];
__device__ float d_grs[BLL*4];

__device__ __forceinline__ float gelu_exact(float x) {
    return 0.5f * x * (1.0f + erff(x * 0.70710678118654752f));
}
// split a float2 into packed bf16x2 hi and residual lo
__device__ __forceinline__ void pack_split(float x0, float x1, uint32_t& hi, uint32_t& lo) {
    uint32_t h;
    asm("cvt.rn.bf16x2.f32 %0, %1, %2;" : "=r"(h) : "f"(x1), "f"(x0));  // lo-half=x0, hi-half=x1
    float h0 = __uint_as_float(h << 16);
    float h1 = __uint_as_float(h & 0xFFFF0000u);
    float r0 = x0 - h0, r1 = x1 - h1;
    uint32_t l;
    asm("cvt.rn.bf16x2.f32 %0, %1, %2;" : "=r"(l) : "f"(r1), "f"(r0));
    hi = h; lo = l;
}

// ---------------- small prep kernels ----------------
__global__ void k_mean(const float* __restrict__ x) {
    int i = blockIdx.x * blockDim.x + threadIdx.x;
    if (i >= BNN) return;
    int b = i / NN, n = i % NN;
    float s = 0.f;
    #pragma unroll
    for (int l = 0; l < LL; ++l) s += x[(b*LL + l)*NN + n];
    d_mean[i] = s * (1.0f / LL);
}

__global__ void k_peT(const float* __restrict__ pr, const float* __restrict__ pw,
                      const float* __restrict__ pb) {
    int i = blockIdx.x * blockDim.x + threadIdx.x;
    if (i >= DD*NN) return;
    int d = i / NN, n = i % NN;
    d_peT[i] = pr[n]*pw[d*3] + pr[NN+n]*pw[d*3+1] + pr[2*NN+n]*pw[d*3+2] + pb[d];
}

__global__ void k_WT2(const float* __restrict__ wp) {
    int idx = blockIdx.x * blockDim.x + threadIdx.x;
    if (idx >= DD*DD*DD) return;
    int d = idx & 127;
    int io = idx >> 7;
    int o = io & 127, ii = io >> 7;
    d_WT2[idx] = wp[(d*128 + ii)*128 + o];
}

// circular conv1d k=3: enc[seq][l][c]
__global__ void k_conv(const float* __restrict__ x, const float* __restrict__ cw) {
    __shared__ float xs[LL + 2];
    int seq = blockIdx.x;
    int b = seq / NN, n = seq % NN;
    float m = d_mean[seq];
    int t = threadIdx.x;   // 128
    if (t < LL) xs[t + 1] = x[(b*LL + t)*NN + n] - m;
    __syncthreads();
    if (t == 0) { xs[0] = xs[LL]; xs[LL+1] = xs[1]; }
    __syncthreads();
    float w0 = cw[t*3], w1 = cw[t*3+1], w2 = cw[t*3+2];
    float* out = d_enc + (size_t)seq * (LL*DD);
    #pragma unroll
    for (int l = 0; l < LL; ++l)
        out[l*DD + t] = w0*xs[l] + w1*xs[l+1] + w2*xs[l+2];
}

// LayerNorm over rows of 128 (one warp per row)
__global__ void k_ln(const float* __restrict__ X, float* __restrict__ Y,
                     const float* __restrict__ g, const float* __restrict__ bta) {
    int warp = (blockIdx.x * blockDim.x + threadIdx.x) >> 5;
    int lane = threadIdx.x & 31;
    const float* xr = X + (size_t)warp * DD;
    float4 v = *(const float4*)(xr + lane*4);
    float s = v.x + v.y + v.z + v.w;
    float sq = v.x*v.x + v.y*v.y + v.z*v.z + v.w*v.w;
    #pragma unroll
    for (int o = 16; o; o >>= 1) {
        s  += __shfl_xor_sync(~0u, s, o);
        sq += __shfl_xor_sync(~0u, sq, o);
    }
    float mu = s * (1.0f/DD);
    float var = sq * (1.0f/DD) - mu*mu;
    float rs = rsqrtf(var + 1e-5f);
    float4 gg = *(const float4*)(g + lane*4);
    float4 bb = *(const float4*)(bta + lane*4);
    float4 o4;
    o4.x = (v.x - mu)*rs*gg.x + bb.x;
    o4.y = (v.y - mu)*rs*gg.y + bb.y;
    o4.z = (v.z - mu)*rs*gg.z + bb.z;
    o4.w = (v.w - mu)*rs*gg.w + bb.w;
    *(float4*)(Y + (size_t)warp*DD + lane*4) = o4;
}

// ---------------- per-sequence linear attention (softmaxes fused) ----------------
// q = softmax_row(qraw)*d^-0.5 ; kk = softmax_col(kraw) ;
// ctx = kk^T @ v ; att_pre = q @ ctx -> d_qb (wo projection is a big GEMM)
#define WPAD 132
#define ATTN_SMEM ((6144*3 + 128*WPAD) * 4)
__global__ void __launch_bounds__(256, 1) k_attn() {
    extern __shared__ float sm[];
    float* Q  = sm;
    float* KK = sm + 6144;
    float* V  = sm + 12288;
    float* W  = sm + 18432;    // ctx 128 x WPAD
    int seq = blockIdx.x, tid = threadIdx.x;
    size_t base = (size_t)seq * 6144;
    for (int i = tid; i < 6144; i += 256) {
        Q[i] = d_qb[base+i]; KK[i] = d_kb[base+i]; V[i] = d_vb[base+i];
    }
    __syncthreads();
    int te = tid & 31, tg = tid >> 5;
    // Q row softmax (48 rows x 128) * d^-0.5 : warp tg handles rows tg*6..tg*6+5
    for (int l = tg*6; l < tg*6+6; ++l) {
        float4 v = *(float4*)&Q[l*128 + te*4];
        float mx = fmaxf(fmaxf(v.x, v.y), fmaxf(v.z, v.w));
        #pragma unroll
        for (int o = 16; o; o >>= 1) mx = fmaxf(mx, __shfl_xor_sync(~0u, mx, o));
        v.x = expf(v.x - mx); v.y = expf(v.y - mx);
        v.z = expf(v.z - mx); v.w = expf(v.w - mx);
        float s = v.x + v.y + v.z + v.w;
        #pragma unroll
        for (int o = 16; o; o >>= 1) s += __shfl_xor_sync(~0u, s, o);
        float f = 0.08838834764831845f / s;
        v.x *= f; v.y *= f; v.z *= f; v.w *= f;
        *(float4*)&Q[l*128 + te*4] = v;
    }
    // K col softmax over L (threads 0..127 each own a column)
    if (tid < 128) {
        int c = tid;
        float mx = -1e30f;
        #pragma unroll
        for (int l = 0; l < LL; ++l) mx = fmaxf(mx, KK[l*128 + c]);
        float s = 0.f;
        float ev[LL];
        #pragma unroll
        for (int l = 0; l < LL; ++l) { ev[l] = expf(KK[l*128 + c] - mx); s += ev[l]; }
        float inv = 1.0f / s;
        #pragma unroll
        for (int l = 0; l < LL; ++l) KK[l*128 + c] = ev[l] * inv;
    }
    __syncthreads();
    // ctx[dd][e] = sum_l KK[l][dd]*V[l][e]
    #pragma unroll
    for (int it = 0; it < 4; ++it) {
        int dd0 = (tg + it*8) * 4, e0 = te * 4;
        float a[4][4] = {};
        #pragma unroll
        for (int l = 0; l < LL; ++l) {
            float4 kf = *(float4*)&KK[l*128 + dd0];
            float4 vf = *(float4*)&V[l*128 + e0];
            a[0][0]+=kf.x*vf.x; a[0][1]+=kf.x*vf.y; a[0][2]+=kf.x*vf.z; a[0][3]+=kf.x*vf.w;
            a[1][0]+=kf.y*vf.x; a[1][1]+=kf.y*vf.y; a[1][2]+=kf.y*vf.z; a[1][3]+=kf.y*vf.w;
            a[2][0]+=kf.z*vf.x; a[2][1]+=kf.z*vf.y; a[2][2]+=kf.z*vf.z; a[2][3]+=kf.z*vf.w;
            a[3][0]+=kf.w*vf.x; a[3][1]+=kf.w*vf.y; a[3][2]+=kf.w*vf.z; a[3][3]+=kf.w*vf.w;
        }
        #pragma unroll
        for (int j = 0; j < 4; ++j)
            *(float4*)&W[(dd0+j)*WPAD + e0] = make_float4(a[j][0], a[j][1], a[j][2], a[j][3]);
    }
    __syncthreads();
    // att_pre[l][e] = sum_dd Q[l][dd]*ctx[dd][e] -> write to d_qb
    #pragma unroll
    for (int it = 0; it < 2; ++it) {
        int tl = tg + it*8;
        if (tl < 12) {
            int l0 = tl*4, e0 = te*4;
            float a[4][4] = {};
            #pragma unroll
            for (int dd = 0; dd < 128; ++dd) {
                float4 wf = *(float4*)&W[dd*WPAD + e0];
                float q0 = Q[(l0+0)*128+dd], q1 = Q[(l0+1)*128+dd];
                float q2 = Q[(l0+2)*128+dd], q3 = Q[(l0+3)*128+dd];
                a[0][0]+=q0*wf.x; a[0][1]+=q0*wf.y; a[0][2]+=q0*wf.z; a[0][3]+=q0*wf.w;
                a[1][0]+=q1*wf.x; a[1][1]+=q1*wf.y; a[1][2]+=q1*wf.z; a[1][3]+=q1*wf.w;
                a[2][0]+=q2*wf.x; a[2][1]+=q2*wf.y; a[2][2]+=q2*wf.z; a[2][3]+=q2*wf.w;
                a[3][0]+=q3*wf.x; a[3][1]+=q3*wf.y; a[3][2]+=q3*wf.z; a[3][3]+=q3*wf.w;
            }
            #pragma unroll
            for (int j = 0; j < 4; ++j)
                *(float4*)&d_qb[base + (l0+j)*128 + e0] =
                    make_float4(a[j][0], a[j][1], a[j][2], a[j][3]);
        }
    }
}

// ---------------- 3x-bf16 split tensor-core GEMM: C = epi( A @ B^T ) ----------------
// fp32 smem tiles; hi/lo bf16 split at fragment load; acc += ah*bh + ah*bl + al*bh.
// epi: 0 store, 2 gelu(x+bias), 3 C += x (+bias)
#define TGK 16
#define TGP 20   // padded k-stride (floats)
__global__ void __launch_bounds__(256) tgemm(
    const float* __restrict__ A, const float* __restrict__ B, float* __restrict__ C,
    int M, int N, int K, const float* __restrict__ bias, int epi)
{
    __shared__ float As[2][128][TGP];
    __shared__ float Bs[2][128][TGP];
    int tid = threadIdx.x;
    int m0 = blockIdx.y * 128, n0 = blockIdx.x * 128;
    int lrow = tid >> 1;            // 0..127
    int lk   = (tid & 1) * 8;       // 0 or 8
    int warp = tid >> 5, lane = tid & 31;
    int wm = (warp >> 2) * 64, wn = (warp & 3) * 32;
    int g = lane >> 2, tig = lane & 3;

    float acc[4][4][4];
    #pragma unroll
    for (int a = 0; a < 4; ++a)
        #pragma unroll
        for (int b = 0; b < 4; ++b)
            #pragma unroll
            for (int c = 0; c < 4; ++c) acc[a][b][c] = 0.f;

    int nk = (K + TGK - 1) / TGK;
    const float* Arow = A + (size_t)(m0 + lrow) * K;
    const float* Brow = B + (size_t)(n0 + lrow) * K;
    bool mok = (m0 + lrow) < M;
    bool nok = (n0 + lrow) < N;

    float ra[8], rb[8];
    {
        int k = lk;
        #pragma unroll
        for (int j = 0; j < 8; j += 4) {
            float4 av = make_float4(0,0,0,0), bv = make_float4(0,0,0,0);
            if (mok && (k + j) < K) av = *(const float4*)(Arow + k + j);
            if (nok && (k + j) < K) bv = *(const float4*)(Brow + k + j);
            ra[j]=av.x; ra[j+1]=av.y; ra[j+2]=av.z; ra[j+3]=av.w;
            rb[j]=bv.x; rb[j+1]=bv.y; rb[j+2]=bv.z; rb[j+3]=bv.w;
        }
        #pragma unroll
        for (int j = 0; j < 8; ++j) {
            As[0][lrow][lk+j] = ra[j];
            Bs[0][lrow][lk+j] = rb[j];
        }
    }
    __syncthreads();

    int s = 0;
    for (int kt = 0; kt < nk; ++kt) {
        bool nxt = (kt + 1) < nk;
        if (nxt) {
            int k = (kt + 1) * TGK + lk;
            #pragma unroll
            for (int j = 0; j < 8; j += 4) {
                float4 av = make_float4(0,0,0,0), bv = make_float4(0,0,0,0);
                if (mok && (k + j) < K) av = *(const float4*)(Arow + k + j);
                if (nok && (k + j) < K) bv = *(const float4*)(Brow + k + j);
                ra[j]=av.x; ra[j+1]=av.y; ra[j+2]=av.z; ra[j+3]=av.w;
                rb[j]=bv.x; rb[j+1]=bv.y; rb[j+2]=bv.z; rb[j+3]=bv.w;
            }
        }
        // fragments for this k16 tile
        {
            uint32_t ah[4][4], al[4][4], bh[4][2], bl[4][2];
            #pragma unroll
            for (int mi = 0; mi < 4; ++mi) {
                int r = wm + mi*16 + g;
                float2 p;
                p = *(float2*)&As[s][r  ][2*tig  ]; pack_split(p.x, p.y, ah[mi][0], al[mi][0]);
                p = *(float2*)&As[s][r+8][2*tig  ]; pack_split(p.x, p.y, ah[mi][1], al[mi][1]);
                p = *(float2*)&As[s][r  ][2*tig+8]; pack_split(p.x, p.y, ah[mi][2], al[mi][2]);
                p = *(float2*)&As[s][r+8][2*tig+8]; pack_split(p.x, p.y, ah[mi][3], al[mi][3]);
            }
            #pragma unroll
            for (int ni = 0; ni < 4; ++ni) {
                int r = wn + ni*8 + g;
                float2 p;
                p = *(float2*)&Bs[s][r][2*tig  ]; pack_split(p.x, p.y, bh[ni][0], bl[ni][0]);
                p = *(float2*)&Bs[s][r][2*tig+8]; pack_split(p.x, p.y, bh[ni][1], bl[ni][1]);
            }
            #pragma unroll
            for (int mi = 0; mi < 4; ++mi)
                #pragma unroll
                for (int ni = 0; ni < 4; ++ni) {
                    asm volatile(
                        "mma.sync.aligned.m16n8k16.row.col.f32.bf16.bf16.f32 "
                        "{%0,%1,%2,%3}, {%4,%5,%6,%7}, {%8,%9}, {%0,%1,%2,%3};"
                        : "+f"(acc[mi][ni][0]), "+f"(acc[mi][ni][1]),
                          "+f"(acc[mi][ni][2]), "+f"(acc[mi][ni][3])
                        : "r"(ah[mi][0]), "r"(ah[mi][1]), "r"(ah[mi][2]), "r"(ah[mi][3]),
                          "r"(bl[ni][0]), "r"(bl[ni][1]));
                    asm volatile(
                        "mma.sync.aligned.m16n8k16.row.col.f32.bf16.bf16.f32 "
                        "{%0,%1,%2,%3}, {%4,%5,%6,%7}, {%8,%9}, {%0,%1,%2,%3};"
                        : "+f"(acc[mi][ni][0]), "+f"(acc[mi][ni][1]),
                          "+f"(acc[mi][ni][2]), "+f"(acc[mi][ni][3])
                        : "r"(al[mi][0]), "r"(al[mi][1]), "r"(al[mi][2]), "r"(al[mi][3]),
                          "r"(bh[ni][0]), "r"(bh[ni][1]));
                    asm volatile(
                        "mma.sync.aligned.m16n8k16.row.col.f32.bf16.bf16.f32 "
                        "{%0,%1,%2,%3}, {%4,%5,%6,%7}, {%8,%9}, {%0,%1,%2,%3};"
                        : "+f"(acc[mi][ni][0]), "+f"(acc[mi][ni][1]),
                          "+f"(acc[mi][ni][2]), "+f"(acc[mi][ni][3])
                        : "r"(ah[mi][0]), "r"(ah[mi][1]), "r"(ah[mi][2]), "r"(ah[mi][3]),
                          "r"(bh[ni][0]), "r"(bh[ni][1]));
                }
        }
        if (nxt) {
            #pragma unroll
            for (int j = 0; j < 8; ++j) {
                As[s^1][lrow][lk+j] = ra[j];
                Bs[s^1][lrow][lk+j] = rb[j];
            }
        }
        __syncthreads();
        s ^= 1;
    }

    // epilogue
    #pragma unroll
    for (int mi = 0; mi < 4; ++mi) {
        #pragma unroll
        for (int ni = 0; ni < 4; ++ni) {
            int n = n0 + wn + ni*8 + tig*2;
            float bv0 = 0.f, bv1 = 0.f;
            if (bias) { bv0 = bias[n]; bv1 = bias[n+1]; }
            #pragma unroll
            for (int half = 0; half < 2; ++half) {
                int m = m0 + wm + mi*16 + g + half*8;
                if (m >= M) continue;
                float r0 = acc[mi][ni][half*2+0] + bv0;
                float r1 = acc[mi][ni][half*2+1] + bv1;
                size_t off = (size_t)m * N + n;
                if (epi == 2) { r0 = gelu_exact(r0); r1 = gelu_exact(r1); }
                if (epi == 3) {
                    float2 cur = *(float2*)(C + off);
                    r0 += cur.x; r1 += cur.y;
                }
                *(float2*)(C + off) = make_float2(r0, r1);
            }
        }
    }
}

// ---------------- transpose enc -> X[(bl*128+d)][n] ----------------
__global__ void k_transpose() {   // grid (94, 96), 256 threads
    __shared__ float T[32*129];
    int n0 = blockIdx.x * 32;
    int bl = blockIdx.y;
    int b = bl / LL, l = bl % LL;
    int tid = threadIdx.x;
    int nrem = NN - n0; if (nrem > 32) nrem = 32;
    for (int i = tid; i < 32*128; i += 256) {
        int r = i >> 7, c = i & 127;
        if (r < nrem)
            T[r*129 + c] = d_enc[((size_t)(b*NN + n0 + r))*6144 + l*128 + c];
    }
    __syncthreads();
    for (int i = tid; i < 128*32; i += 256) {
        int dd = i >> 5, j = i & 31;
        if (j < nrem)
            d_X[((size_t)(bl*128 + dd))*NN + n0 + j] = T[j*129 + dd];
    }
}

// ---------------- per-node grouped GEMM: gout[n] = agg[n](96x128) @ pw[n](128x128) ----------------
#define GRP_SMEM ((128*WPAD + 96*128) * 4)
__global__ void __launch_bounds__(256, 1) k_grouped() {
    extern __shared__ float sm[];
    float* Wsm = sm;               // [i][o] padded WPAD
    float* Asm = sm + 128*WPAD;    // [bl][i]
    int n = blockIdx.x, tid = threadIdx.x;
    const float* pw = d_pw + (size_t)n * 16384;
    const float* ag = d_agg + (size_t)n * 12288;
    for (int i = tid; i < 16384; i += 256) {
        int ii = i >> 7, o = i & 127;
        Wsm[ii*WPAD + o] = pw[i];
    }
    for (int i = tid; i < 12288; i += 256) Asm[i] = ag[i];
    __syncthreads();
    int tc = tid & 31, tg = tid >> 5;
    #pragma unroll
    for (int it = 0; it < 3; ++it) {
        int bl0 = (tg + it*8) * 4, c0 = tc * 4;
        float a[4][4] = {};
        #pragma unroll
        for (int i = 0; i < 128; ++i) {
            float4 wf = *(float4*)&Wsm[i*WPAD + c0];
            float a0 = Asm[(bl0+0)*128+i], a1 = Asm[(bl0+1)*128+i];
            float a2 = Asm[(bl0+2)*128+i], a3 = Asm[(bl0+3)*128+i];
            a[0][0]+=a0*wf.x; a[0][1]+=a0*wf.y; a[0][2]+=a0*wf.z; a[0][3]+=a0*wf.w;
            a[1][0]+=a1*wf.x; a[1][1]+=a1*wf.y; a[1][2]+=a1*wf.z; a[1][3]+=a1*wf.w;
            a[2][0]+=a2*wf.x; a[2][1]+=a2*wf.y; a[2][2]+=a2*wf.z; a[2][3]+=a2*wf.w;
            a[3][0]+=a3*wf.x; a[3][1]+=a3*wf.y; a[3][2]+=a3*wf.z; a[3][3]+=a3*wf.w;
        }
        #pragma unroll
        for (int j = 0; j < 4; ++j)
            *(float4*)&d_gout[(size_t)n*12288 + (bl0+j)*128 + c0] =
                make_float4(a[j][0], a[j][1], a[j][2], a[j][3]);
    }
}

// ---------------- GroupNorm stats per (bl, group) ----------------
__global__ void k_gnstats() {   // grid BLL*4
    __shared__ float rs[256], rq[256];
    int bl = blockIdx.x >> 2, g = blockIdx.x & 3;
    int tid = threadIdx.x;
    float s = 0.f, q = 0.f;
    for (int i = tid; i < NN*32; i += 256) {
        int n = i >> 5, o = i & 31;
        float v = d_gout[(size_t)n*12288 + bl*128 + g*32 + o];
        s += v; q += v*v;
    }
    rs[tid] = s; rq[tid] = q;
    __syncthreads();
    for (int st = 128; st; st >>= 1) {
        if (tid < st) { rs[tid] += rs[tid+st]; rq[tid] += rq[tid+st]; }
        __syncthreads();
    }
    if (tid == 0) {
        const float inv = 1.0f / (float)(NN*32);
        float mu = rs[0] * inv;
        float var = rq[0] * inv - mu*mu;
        d_gmu[blockIdx.x] = mu;
        d_grs[blockIdx.x] = rsqrtf(var + 1e-5f);
    }
}

// ---------------- fused GN-apply + SiLU proj + time proj + mean add ----------------
__global__ void k_final(const float* __restrict__ gg, const float* __restrict__ gb,
                        const float* __restrict__ p2w, const float* __restrict__ p2b,
                        const float* __restrict__ p1w, const float* __restrict__ p1b,
                        float* __restrict__ out) {
    __shared__ float Xs[6144];
    __shared__ float Ss[LL];
    int bn = blockIdx.x;
    int b = bn / NN, n = bn % NN;
    int tid = threadIdx.x;   // 256
    for (int i = tid; i < 6144; i += 256) {
        int l = i >> 7, c = i & 127;
        int bl = b*LL + l, g = c >> 5;
        float v = d_gout[(size_t)n*12288 + bl*128 + c];
        Xs[i] = (v - d_gmu[bl*4+g]) * d_grs[bl*4+g] * gg[c] + gb[c];
    }
    __syncthreads();
    int lane = tid & 31, w = tid >> 5;
    for (int l = w*6; l < w*6+6; ++l) {
        float s = Xs[l*128+lane]*p2w[lane] + Xs[l*128+lane+32]*p2w[lane+32]
                + Xs[l*128+lane+64]*p2w[lane+64] + Xs[l*128+lane+96]*p2w[lane+96];
        #pragma unroll
        for (int o = 16; o; o >>= 1) s += __shfl_xor_sync(~0u, s, o);
        if (lane == 0) {
            float z = s + p2b[0];
            Ss[l] = z / (1.0f + expf(-z));
        }
    }
    __syncthreads();
    if (tid < L_OUT) {
        float acc = p1b[tid];
        #pragma unroll
        for (int l = 0; l < LL; ++l) acc += Ss[l] * p1w[tid*LL + l];
        out[((size_t)(b*L_OUT + tid))*NN + n] = acc + d_mean[bn];
    }
}

// ---------------- launcher ----------------
extern "C" void kernel_launch(void* const* d_in, const int* in_sizes, int n_in,
                              void* d_out, int out_size) {
    const float* x_enc   = (const float*)d_in[0];
    const float* adj     = (const float*)d_in[1];
    const float* pe_raw  = (const float*)d_in[2];
    const float* conv_w  = (const float*)d_in[3];
    const float* pos_w   = (const float*)d_in[4];
    const float* pos_b   = (const float*)d_in[5];
    const float* wq      = (const float*)d_in[6];
    const float* wk      = (const float*)d_in[7];
    const float* wv      = (const float*)d_in[8];
    const float* wo      = (const float*)d_in[9];
    const float* ln1_g   = (const float*)d_in[10];
    const float* ln1_b   = (const float*)d_in[11];
    const float* ff_w1   = (const float*)d_in[12];
    const float* ff_b1   = (const float*)d_in[13];
    const float* ff_w2   = (const float*)d_in[14];
    const float* ff_b2   = (const float*)d_in[15];
    const float* ln2_g   = (const float*)d_in[16];
    const float* ln2_b   = (const float*)d_in[17];
    const float* wpool   = (const float*)d_in[18];
    const float* gn_g    = (const float*)d_in[19];
    const float* gn_b    = (const float*)d_in[20];
    const float* p2_w    = (const float*)d_in[21];
    const float* p2_b    = (const float*)d_in[22];
    const float* p1_w    = (const float*)d_in[23];
    const float* p1_b    = (const float*)d_in[24];
    float* out = (float*)d_out;

    float *p_enc, *p_h, *p_q, *p_k, *p_v, *p_ff, *p_X, *p_agg, *p_pe2, *p_pw, *p_peT, *p_WT2;
    cudaGetSymbolAddress((void**)&p_enc, d_enc);
    cudaGetSymbolAddress((void**)&p_h,   d_h);
    cudaGetSymbolAddress((void**)&p_q,   d_qb);
    cudaGetSymbolAddress((void**)&p_k,   d_kb);
    cudaGetSymbolAddress((void**)&p_v,   d_vb);
    cudaGetSymbolAddress((void**)&p_ff,  d_ff);
    cudaGetSymbolAddress((void**)&p_X,   d_X);
    cudaGetSymbolAddress((void**)&p_agg, d_agg);
    cudaGetSymbolAddress((void**)&p_pe2, d_pe2);
    cudaGetSymbolAddress((void**)&p_pw,  d_pw);
    cudaGetSymbolAddress((void**)&p_peT, d_peT);
    cudaGetSymbolAddress((void**)&p_WT2, d_WT2);

    cudaFuncSetAttribute(k_attn,    cudaFuncAttributeMaxDynamicSharedMemorySize, ATTN_SMEM);
    cudaFuncSetAttribute(k_grouped, cudaFuncAttributeMaxDynamicSharedMemorySize, GRP_SMEM);

    // prep
    k_mean<<<(BNN+255)/256, 256>>>(x_enc);
    k_peT<<<(DD*NN+255)/256, 256>>>(pe_raw, pos_w, pos_b);
    k_WT2<<<(DD*DD*DD+255)/256, 256>>>(wpool);
    k_conv<<<BNN, 128>>>(x_enc, conv_w);

    // temporal transformer
    k_ln<<<ROWS/8, 256>>>(p_enc, p_h, ln1_g, ln1_b);
    tgemm<<<dim3(1, ROWS/128), 256>>>(p_h, wq, p_q, ROWS, 128, 128, nullptr, 0);
    tgemm<<<dim3(1, ROWS/128), 256>>>(p_h, wk, p_k, ROWS, 128, 128, nullptr, 0);
    tgemm<<<dim3(1, ROWS/128), 256>>>(p_h, wv, p_v, ROWS, 128, 128, nullptr, 0);
    k_attn<<<BNN, 256, ATTN_SMEM>>>();
    tgemm<<<dim3(1, ROWS/128), 256>>>(p_q, wo, p_enc, ROWS, 128, 128, nullptr, 3);  // enc += att@wo^T
    k_ln<<<ROWS/8, 256>>>(p_enc, p_h, ln2_g, ln2_b);
    tgemm<<<dim3(4, ROWS/128), 256>>>(p_h, ff_w1, p_ff, ROWS, 512, 128, ff_b1, 2);
    tgemm<<<dim3(1, ROWS/128), 256>>>(p_ff, ff_w2, p_enc, ROWS, 128, 512, ff_b2, 3);

    // spatial GCN
    k_transpose<<<dim3(94, BLL), 256>>>();
    tgemm<<<dim3(1,   24), 256>>>(adj,   p_peT, p_pe2, NN, 128,   NN,  nullptr, 0);
    tgemm<<<dim3(128, 24), 256>>>(p_pe2, p_WT2, p_pw,  NN, 16384, 128, nullptr, 0);
    tgemm<<<dim3(96,  24), 256>>>(adj,   p_X,   p_agg, NN, 12288, NN,  nullptr, 0);
    k_grouped<<<NN, 256, GRP_SMEM>>>();

    // groupnorm + head
    k_gnstats<<<BLL*4, 256>>>();
    k_final<<<BNN, 256>>>(gn_g, gn_b, p2_w, p2_b, p1_w, p1_b, out);
}

// round 5
// speedup vs baseline: 1.6700x; 1.0133x over previous
#include <cuda_runtime.h>
#include <cuda_bf16.h>
#include <math.h>
#include <stdint.h>

#define BB 2
#define LL 48
#define NN 3000
#define DD 128
#define L_OUT 24
#define BNN (BB*NN)          // 6000
#define BLL (BB*LL)          // 96
#define ROWS (BNN*LL)        // 288000 token rows
#define ENC_N (ROWS*DD)      // 36,864,000

typedef __nv_bfloat16 bf16;

// ---------------- scratch (device globals; no runtime allocation) ----------------
__device__ float d_mean[BNN];
__device__ float d_pe2junk; // placeholder
__device__ float d_enc[ENC_N];           // enc[seq][l][c]
__device__ float d_qb[ENC_N];            // q fp32
__device__ float d_kb[ENC_N];
__device__ float d_vb[ENC_N];
__device__ float d_agg[NN*BLL*DD];       // agg[n][bl][i]
__device__ float d_pw[NN*DD*DD];         // pw[n][i][o]
__device__ float d_gout[NN*BLL*DD];      // gout[n][bl][o]
__device__ float d_gmu[BLL*4];
__device__ float d_grs[BLL*4];

// bf16 split pairs
__device__ bf16 d_hh[ENC_N],  d_hl[ENC_N];     // LN output
__device__ bf16 d_qh[ENC_N],  d_ql[ENC_N];     // att_pre
__device__ bf16 d_ffh[ROWS*512], d_ffl[ROWS*512];
__device__ bf16 d_adjh[NN*NN], d_adjl[NN*NN];
__device__ bf16 d_Xh[BLL*DD*NN], d_Xl[BLL*DD*NN];
__device__ bf16 d_peTh[DD*NN], d_peTl[DD*NN];
__device__ bf16 d_WT2h[DD*DD*DD], d_WT2l[DD*DD*DD];
__device__ bf16 d_pe2h[NN*DD], d_pe2l[NN*DD];
// weight pool: [wq|wk|wv|wo|ffw1|ffw2]
#define WPO_Q 0
#define WPO_K 16384
#define WPO_V 32768
#define WPO_O 49152
#define WPO_F1 65536
#define WPO_F2 131072
__device__ bf16 d_wph[196608], d_wpl[196608];

__device__ __forceinline__ float gelu_exact(float x) {
    return 0.5f * x * (1.0f + erff(x * 0.70710678118654752f));
}
// split (x0,x1) into packed bf16x2 hi and residual lo (lo-half = x0)
__device__ __forceinline__ void pack_split(float x0, float x1, uint32_t& hi, uint32_t& lo) {
    uint32_t h;
    asm("cvt.rn.bf16x2.f32 %0, %1, %2;" : "=r"(h) : "f"(x1), "f"(x0));
    float h0 = __uint_as_float(h << 16);
    float h1 = __uint_as_float(h & 0xFFFF0000u);
    float r0 = x0 - h0, r1 = x1 - h1;
    uint32_t l;
    asm("cvt.rn.bf16x2.f32 %0, %1, %2;" : "=r"(l) : "f"(r1), "f"(r0));
    hi = h; lo = l;
}
__device__ __forceinline__ void scalar_split(float v, bf16& h, bf16& l) {
    h = __float2bfloat16_rn(v);
    l = __float2bfloat16_rn(v - __bfloat162float(h));
}

// ---------------- small prep kernels ----------------
__global__ void k_mean(const float* __restrict__ x) {
    int i = blockIdx.x * blockDim.x + threadIdx.x;
    if (i >= BNN) return;
    int b = i / NN, n = i % NN;
    float s = 0.f;
    #pragma unroll
    for (int l = 0; l < LL; ++l) s += x[(b*LL + l)*NN + n];
    d_mean[i] = s * (1.0f / LL);
}

__global__ void k_split(const float* __restrict__ in, bf16* __restrict__ h,
                        bf16* __restrict__ l, int n) {
    int i = blockIdx.x * blockDim.x + threadIdx.x;
    if (i >= n) return;
    scalar_split(in[i], h[i], l[i]);
}

__global__ void k_peT(const float* __restrict__ pr, const float* __restrict__ pw,
                      const float* __restrict__ pb) {
    int i = blockIdx.x * blockDim.x + threadIdx.x;
    if (i >= DD*NN) return;
    int d = i / NN, n = i % NN;
    float v = pr[n]*pw[d*3] + pr[NN+n]*pw[d*3+1] + pr[2*NN+n]*pw[d*3+2] + pb[d];
    scalar_split(v, d_peTh[i], d_peTl[i]);
}

__global__ void k_WT2(const float* __restrict__ wp) {
    int idx = blockIdx.x * blockDim.x + threadIdx.x;
    if (idx >= DD*DD*DD) return;
    int d = idx & 127;
    int io = idx >> 7;
    int o = io & 127, ii = io >> 7;
    scalar_split(wp[(d*128 + ii)*128 + o], d_WT2h[idx], d_WT2l[idx]);
}

// circular conv1d k=3: enc[seq][l][c]
__global__ void k_conv(const float* __restrict__ x, const float* __restrict__ cw) {
    __shared__ float xs[LL + 2];
    int seq = blockIdx.x;
    int b = seq / NN, n = seq % NN;
    float m = d_mean[seq];
    int t = threadIdx.x;   // 128
    if (t < LL) xs[t + 1] = x[(b*LL + t)*NN + n] - m;
    __syncthreads();
    if (t == 0) { xs[0] = xs[LL]; xs[LL+1] = xs[1]; }
    __syncthreads();
    float w0 = cw[t*3], w1 = cw[t*3+1], w2 = cw[t*3+2];
    float* out = d_enc + (size_t)seq * (LL*DD);
    #pragma unroll
    for (int l = 0; l < LL; ++l)
        out[l*DD + t] = w0*xs[l] + w1*xs[l+1] + w2*xs[l+2];
}

// LayerNorm over rows of 128 (one warp per row), writes split bf16 pair
__global__ void k_ln(const float* __restrict__ X,
                     const float* __restrict__ g, const float* __restrict__ bta) {
    int warp = (blockIdx.x * blockDim.x + threadIdx.x) >> 5;
    int lane = threadIdx.x & 31;
    const float* xr = X + (size_t)warp * DD;
    float4 v = *(const float4*)(xr + lane*4);
    float s = v.x + v.y + v.z + v.w;
    float sq = v.x*v.x + v.y*v.y + v.z*v.z + v.w*v.w;
    #pragma unroll
    for (int o = 16; o; o >>= 1) {
        s  += __shfl_xor_sync(~0u, s, o);
        sq += __shfl_xor_sync(~0u, sq, o);
    }
    float mu = s * (1.0f/DD);
    float var = sq * (1.0f/DD) - mu*mu;
    float rs = rsqrtf(var + 1e-5f);
    float4 gg = *(const float4*)(g + lane*4);
    float4 bb = *(const float4*)(bta + lane*4);
    float o0 = (v.x - mu)*rs*gg.x + bb.x;
    float o1 = (v.y - mu)*rs*gg.y + bb.y;
    float o2 = (v.z - mu)*rs*gg.z + bb.z;
    float o3 = (v.w - mu)*rs*gg.w + bb.w;
    uint32_t h01, l01, h23, l23;
    pack_split(o0, o1, h01, l01);
    pack_split(o2, o3, h23, l23);
    ((uint2*)d_hh)[(size_t)warp*32 + lane] = make_uint2(h01, h23);
    ((uint2*)d_hl)[(size_t)warp*32 + lane] = make_uint2(l01, l23);
}

// ---------------- per-sequence linear attention (softmaxes fused) ----------------
#define WPAD 132
#define ATTN_SMEM ((6144*3 + 128*WPAD) * 4)
__global__ void __launch_bounds__(256, 1) k_attn() {
    extern __shared__ float sm[];
    float* Q  = sm;
    float* KK = sm + 6144;
    float* V  = sm + 12288;
    float* W  = sm + 18432;    // ctx 128 x WPAD
    int seq = blockIdx.x, tid = threadIdx.x;
    size_t base = (size_t)seq * 6144;
    for (int i = tid; i < 6144; i += 256) {
        Q[i] = d_qb[base+i]; KK[i] = d_kb[base+i]; V[i] = d_vb[base+i];
    }
    __syncthreads();
    int te = tid & 31, tg = tid >> 5;
    // Q row softmax * d^-0.5
    for (int l = tg*6; l < tg*6+6; ++l) {
        float4 v = *(float4*)&Q[l*128 + te*4];
        float mx = fmaxf(fmaxf(v.x, v.y), fmaxf(v.z, v.w));
        #pragma unroll
        for (int o = 16; o; o >>= 1) mx = fmaxf(mx, __shfl_xor_sync(~0u, mx, o));
        v.x = expf(v.x - mx); v.y = expf(v.y - mx);
        v.z = expf(v.z - mx); v.w = expf(v.w - mx);
        float s = v.x + v.y + v.z + v.w;
        #pragma unroll
        for (int o = 16; o; o >>= 1) s += __shfl_xor_sync(~0u, s, o);
        float f = 0.08838834764831845f / s;
        v.x *= f; v.y *= f; v.z *= f; v.w *= f;
        *(float4*)&Q[l*128 + te*4] = v;
    }
    // K col softmax over L
    if (tid < 128) {
        int c = tid;
        float mx = -1e30f;
        #pragma unroll
        for (int l = 0; l < LL; ++l) mx = fmaxf(mx, KK[l*128 + c]);
        float s = 0.f;
        float ev[LL];
        #pragma unroll
        for (int l = 0; l < LL; ++l) { ev[l] = expf(KK[l*128 + c] - mx); s += ev[l]; }
        float inv = 1.0f / s;
        #pragma unroll
        for (int l = 0; l < LL; ++l) KK[l*128 + c] = ev[l] * inv;
    }
    __syncthreads();
    // ctx[dd][e] = sum_l KK[l][dd]*V[l][e]
    #pragma unroll
    for (int it = 0; it < 4; ++it) {
        int dd0 = (tg + it*8) * 4, e0 = te * 4;
        float a[4][4] = {};
        #pragma unroll
        for (int l = 0; l < LL; ++l) {
            float4 kf = *(float4*)&KK[l*128 + dd0];
            float4 vf = *(float4*)&V[l*128 + e0];
            a[0][0]+=kf.x*vf.x; a[0][1]+=kf.x*vf.y; a[0][2]+=kf.x*vf.z; a[0][3]+=kf.x*vf.w;
            a[1][0]+=kf.y*vf.x; a[1][1]+=kf.y*vf.y; a[1][2]+=kf.y*vf.z; a[1][3]+=kf.y*vf.w;
            a[2][0]+=kf.z*vf.x; a[2][1]+=kf.z*vf.y; a[2][2]+=kf.z*vf.z; a[2][3]+=kf.z*vf.w;
            a[3][0]+=kf.w*vf.x; a[3][1]+=kf.w*vf.y; a[3][2]+=kf.w*vf.z; a[3][3]+=kf.w*vf.w;
        }
        #pragma unroll
        for (int j = 0; j < 4; ++j)
            *(float4*)&W[(dd0+j)*WPAD + e0] = make_float4(a[j][0], a[j][1], a[j][2], a[j][3]);
    }
    __syncthreads();
    // att_pre[l][e] = sum_dd Q[l][dd]*ctx[dd][e] -> split store to d_qh/d_ql
    #pragma unroll
    for (int it = 0; it < 2; ++it) {
        int tl = tg + it*8;
        if (tl < 12) {
            int l0 = tl*4, e0 = te*4;
            float a[4][4] = {};
            #pragma unroll
            for (int dd = 0; dd < 128; ++dd) {
                float4 wf = *(float4*)&W[dd*WPAD + e0];
                float q0 = Q[(l0+0)*128+dd], q1 = Q[(l0+1)*128+dd];
                float q2 = Q[(l0+2)*128+dd], q3 = Q[(l0+3)*128+dd];
                a[0][0]+=q0*wf.x; a[0][1]+=q0*wf.y; a[0][2]+=q0*wf.z; a[0][3]+=q0*wf.w;
                a[1][0]+=q1*wf.x; a[1][1]+=q1*wf.y; a[1][2]+=q1*wf.z; a[1][3]+=q1*wf.w;
                a[2][0]+=q2*wf.x; a[2][1]+=q2*wf.y; a[2][2]+=q2*wf.z; a[2][3]+=q2*wf.w;
                a[3][0]+=q3*wf.x; a[3][1]+=q3*wf.y; a[3][2]+=q3*wf.z; a[3][3]+=q3*wf.w;
            }
            #pragma unroll
            for (int j = 0; j < 4; ++j) {
                uint32_t h01,l01,h23,l23;
                pack_split(a[j][0], a[j][1], h01, l01);
                pack_split(a[j][2], a[j][3], h23, l23);
                size_t w4 = (base + (size_t)(l0+j)*128 + e0) >> 2;
                ((uint2*)d_qh)[w4] = make_uint2(h01, h23);
                ((uint2*)d_ql)[w4] = make_uint2(l01, l23);
            }
        }
    }
}

// ---------------- 3x-bf16 split GEMM with pre-split inputs ----------------
// C[m][n] = epi( sum_k A[m][k]*B[n][k] ), A = Ah+Al, B = Bh+Bl (bf16 pairs)
// epi: 0 store fp32, 2 gelu(x+bias)->split bf16 out, 3 C += x(+bias), 5 split bf16 out
#define TGW 12   // uint32 row stride in smem (8 words data + 4 pad; ≡4 mod 32 pattern-free)
#define TG_SMEM (2*4*128*TGW*4)   // 49152 bytes
__global__ void __launch_bounds__(256) tgemm(
    const bf16* __restrict__ Ah, const bf16* __restrict__ Al,
    const bf16* __restrict__ Bh, const bf16* __restrict__ Bl,
    float* __restrict__ C, bf16* __restrict__ Oh, bf16* __restrict__ Ol,
    int M, int N, int K, const float* __restrict__ bias, int epi)
{
    extern __shared__ uint32_t SMu[];
    const int tid = threadIdx.x;
    const int m0 = blockIdx.y * 128, n0 = blockIdx.x * 128;
    const int lrow = tid >> 1, comp = tid & 1;
    const int warp = tid >> 5, lane = tid & 31;
    const int wm = (warp >> 2) * 64, wn = (warp & 3) * 32;
    const int g = lane >> 2, tig = lane & 3;

    const bf16* Arow = (comp ? Al : Ah) + (size_t)(m0 + lrow) * K;
    const bf16* Brow = (comp ? Bl : Bh) + (size_t)(n0 + lrow) * K;
    const bool mok = (m0 + lrow) < M;

    float acc[4][4][4];
    #pragma unroll
    for (int a = 0; a < 4; ++a)
        #pragma unroll
        for (int b = 0; b < 4; ++b)
            #pragma unroll
            for (int c = 0; c < 4; ++c) acc[a][b][c] = 0.f;

    const int nk = (K + 15) / 16;
    uint4 pa0, pa1, pb0, pb1;
    const uint4 zz = make_uint4(0,0,0,0);

    // fetch tile kt into registers
    #define FETCH(kt) do { \
        int k_ = (kt)*16; \
        pa0 = (mok && k_+8  <= K) ? *(const uint4*)(Arow + k_    ) : zz; \
        pa1 = (mok && k_+16 <= K) ? *(const uint4*)(Arow + k_ + 8) : zz; \
        pb0 = (k_+8  <= K) ? *(const uint4*)(Brow + k_    ) : zz; \
        pb1 = (k_+16 <= K) ? *(const uint4*)(Brow + k_ + 8) : zz; \
    } while (0)
    #define STORE(buf) do { \
        uint32_t* pA = SMu + (((buf)*4 + comp)*128 + lrow)*TGW; \
        pA[0]=pa0.x; pA[1]=pa0.y; pA[2]=pa0.z; pA[3]=pa0.w; \
        pA[4]=pa1.x; pA[5]=pa1.y; pA[6]=pa1.z; pA[7]=pa1.w; \
        uint32_t* pB = SMu + (((buf)*4 + 2 + comp)*128 + lrow)*TGW; \
        pB[0]=pb0.x; pB[1]=pb0.y; pB[2]=pb0.z; pB[3]=pb0.w; \
        pB[4]=pb1.x; pB[5]=pb1.y; pB[6]=pb1.z; pB[7]=pb1.w; \
    } while (0)

    FETCH(0); STORE(0);
    __syncthreads();

    int s = 0;
    for (int kt = 0; kt < nk; ++kt) {
        bool nxt = (kt + 1) < nk;
        if (nxt) FETCH(kt + 1);

        uint32_t ah[4][4], al[4][4], bh[4][2], bl[4][2];
        const uint32_t* Ah_s = SMu + ((s*4 + 0)*128)*TGW;
        const uint32_t* Al_s = SMu + ((s*4 + 1)*128)*TGW;
        const uint32_t* Bh_s = SMu + ((s*4 + 2)*128)*TGW;
        const uint32_t* Bl_s = SMu + ((s*4 + 3)*128)*TGW;
        #pragma unroll
        for (int mi = 0; mi < 4; ++mi) {
            int r = wm + mi*16 + g;
            ah[mi][0] = Ah_s[ r     *TGW + tig    ];
            ah[mi][1] = Ah_s[(r + 8)*TGW + tig    ];
            ah[mi][2] = Ah_s[ r     *TGW + tig + 4];
            ah[mi][3] = Ah_s[(r + 8)*TGW + tig + 4];
            al[mi][0] = Al_s[ r     *TGW + tig    ];
            al[mi][1] = Al_s[(r + 8)*TGW + tig    ];
            al[mi][2] = Al_s[ r     *TGW + tig + 4];
            al[mi][3] = Al_s[(r + 8)*TGW + tig + 4];
        }
        #pragma unroll
        for (int ni = 0; ni < 4; ++ni) {
            int r = wn + ni*8 + g;
            bh[ni][0] = Bh_s[r*TGW + tig    ];
            bh[ni][1] = Bh_s[r*TGW + tig + 4];
            bl[ni][0] = Bl_s[r*TGW + tig    ];
            bl[ni][1] = Bl_s[r*TGW + tig + 4];
        }
        #pragma unroll
        for (int mi = 0; mi < 4; ++mi)
            #pragma unroll
            for (int ni = 0; ni < 4; ++ni) {
                asm volatile(
                    "mma.sync.aligned.m16n8k16.row.col.f32.bf16.bf16.f32 "
                    "{%0,%1,%2,%3}, {%4,%5,%6,%7}, {%8,%9}, {%0,%1,%2,%3};"
                    : "+f"(acc[mi][ni][0]), "+f"(acc[mi][ni][1]),
                      "+f"(acc[mi][ni][2]), "+f"(acc[mi][ni][3])
                    : "r"(ah[mi][0]), "r"(ah[mi][1]), "r"(ah[mi][2]), "r"(ah[mi][3]),
                      "r"(bl[ni][0]), "r"(bl[ni][1]));
                asm volatile(
                    "mma.sync.aligned.m16n8k16.row.col.f32.bf16.bf16.f32 "
                    "{%0,%1,%2,%3}, {%4,%5,%6,%7}, {%8,%9}, {%0,%1,%2,%3};"
                    : "+f"(acc[mi][ni][0]), "+f"(acc[mi][ni][1]),
                      "+f"(acc[mi][ni][2]), "+f"(acc[mi][ni][3])
                    : "r"(al[mi][0]), "r"(al[mi][1]), "r"(al[mi][2]), "r"(al[mi][3]),
                      "r"(bh[ni][0]), "r"(bh[ni][1]));
                asm volatile(
                    "mma.sync.aligned.m16n8k16.row.col.f32.bf16.bf16.f32 "
                    "{%0,%1,%2,%3}, {%4,%5,%6,%7}, {%8,%9}, {%0,%1,%2,%3};"
                    : "+f"(acc[mi][ni][0]), "+f"(acc[mi][ni][1]),
                      "+f"(acc[mi][ni][2]), "+f"(acc[mi][ni][3])
                    : "r"(ah[mi][0]), "r"(ah[mi][1]), "r"(ah[mi][2]), "r"(ah[mi][3]),
                      "r"(bh[ni][0]), "r"(bh[ni][1]));
            }
        if (nxt) STORE(s ^ 1);
        __syncthreads();
        s ^= 1;
    }
    #undef FETCH
    #undef STORE

    // epilogue
    #pragma unroll
    for (int mi = 0; mi < 4; ++mi) {
        #pragma unroll
        for (int ni = 0; ni < 4; ++ni) {
            int n = n0 + wn + ni*8 + tig*2;
            float bv0 = 0.f, bv1 = 0.f;
            if (bias) { bv0 = bias[n]; bv1 = bias[n+1]; }
            #pragma unroll
            for (int half = 0; half < 2; ++half) {
                int m = m0 + wm + mi*16 + g + half*8;
                if (m >= M) continue;
                float r0 = acc[mi][ni][half*2+0] + bv0;
                float r1 = acc[mi][ni][half*2+1] + bv1;
                size_t off = (size_t)m * N + n;
                if (epi == 0) {
                    *(float2*)(C + off) = make_float2(r0, r1);
                } else if (epi == 2) {
                    r0 = gelu_exact(r0); r1 = gelu_exact(r1);
                    uint32_t hp, lp;
                    pack_split(r0, r1, hp, lp);
                    ((uint32_t*)Oh)[off >> 1] = hp;
                    ((uint32_t*)Ol)[off >> 1] = lp;
                } else if (epi == 3) {
                    float2 cur = *(float2*)(C + off);
                    *(float2*)(C + off) = make_float2(r0 + cur.x, r1 + cur.y);
                } else { // 5
                    uint32_t hp, lp;
                    pack_split(r0, r1, hp, lp);
                    ((uint32_t*)Oh)[off >> 1] = hp;
                    ((uint32_t*)Ol)[off >> 1] = lp;
                }
            }
        }
    }
}

// ---------------- transpose enc -> X[(bl*128+d)][n], split bf16 out ----------------
__global__ void k_transpose() {   // grid (94, 96), 256 threads
    __shared__ float T[32*129];
    int n0 = blockIdx.x * 32;
    int bl = blockIdx.y;
    int b = bl / LL, l = bl % LL;
    int tid = threadIdx.x;
    int nrem = NN - n0; if (nrem > 32) nrem = 32;
    for (int i = tid; i < 32*128; i += 256) {
        int r = i >> 7, c = i & 127;
        if (r < nrem)
            T[r*129 + c] = d_enc[((size_t)(b*NN + n0 + r))*6144 + l*128 + c];
    }
    __syncthreads();
    for (int i = tid; i < 128*32; i += 256) {
        int dd = i >> 5, j = i & 31;
        if (j < nrem) {
            float v = T[j*129 + dd];
            size_t o = ((size_t)(bl*128 + dd))*NN + n0 + j;
            scalar_split(v, d_Xh[o], d_Xl[o]);
        }
    }
}

// ---------------- per-node grouped GEMM: gout[n] = agg[n](96x128) @ pw[n](128x128) ----------------
#define GRP_SMEM ((128*WPAD + 96*128) * 4)
__global__ void __launch_bounds__(256, 1) k_grouped() {
    extern __shared__ float sm[];
    float* Wsm = sm;               // [i][o] padded WPAD
    float* Asm = sm + 128*WPAD;    // [bl][i]
    int n = blockIdx.x, tid = threadIdx.x;
    const float* pw = d_pw + (size_t)n * 16384;
    const float* ag = d_agg + (size_t)n * 12288;
    for (int i = tid; i < 16384; i += 256) {
        int ii = i >> 7, o = i & 127;
        Wsm[ii*WPAD + o] = pw[i];
    }
    for (int i = tid; i < 12288; i += 256) Asm[i] = ag[i];
    __syncthreads();
    int tc = tid & 31, tg = tid >> 5;
    #pragma unroll
    for (int it = 0; it < 3; ++it) {
        int bl0 = (tg + it*8) * 4, c0 = tc * 4;
        float a[4][4] = {};
        #pragma unroll
        for (int i = 0; i < 128; ++i) {
            float4 wf = *(float4*)&Wsm[i*WPAD + c0];
            float a0 = Asm[(bl0+0)*128+i], a1 = Asm[(bl0+1)*128+i];
            float a2 = Asm[(bl0+2)*128+i], a3 = Asm[(bl0+3)*128+i];
            a[0][0]+=a0*wf.x; a[0][1]+=a0*wf.y; a[0][2]+=a0*wf.z; a[0][3]+=a0*wf.w;
            a[1][0]+=a1*wf.x; a[1][1]+=a1*wf.y; a[1][2]+=a1*wf.z; a[1][3]+=a1*wf.w;
            a[2][0]+=a2*wf.x; a[2][1]+=a2*wf.y; a[2][2]+=a2*wf.z; a[2][3]+=a2*wf.w;
            a[3][0]+=a3*wf.x; a[3][1]+=a3*wf.y; a[3][2]+=a3*wf.z; a[3][3]+=a3*wf.w;
        }
        #pragma unroll
        for (int j = 0; j < 4; ++j)
            *(float4*)&d_gout[(size_t)n*12288 + (bl0+j)*128 + c0] =
                make_float4(a[j][0], a[j][1], a[j][2], a[j][3]);
    }
}

// ---------------- GroupNorm stats per (bl, group) ----------------
__global__ void k_gnstats() {   // grid BLL*4
    __shared__ float rs[256], rq[256];
    int bl = blockIdx.x >> 2, g = blockIdx.x & 3;
    int tid = threadIdx.x;
    float s = 0.f, q = 0.f;
    for (int i = tid; i < NN*32; i += 256) {
        int n = i >> 5, o = i & 31;
        float v = d_gout[(size_t)n*12288 + bl*128 + g*32 + o];
        s += v; q += v*v;
    }
    rs[tid] = s; rq[tid] = q;
    __syncthreads();
    for (int st = 128; st; st >>= 1) {
        if (tid < st) { rs[tid] += rs[tid+st]; rq[tid] += rq[tid+st]; }
        __syncthreads();
    }
    if (tid == 0) {
        const float inv = 1.0f / (float)(NN*32);
        float mu = rs[0] * inv;
        float var = rq[0] * inv - mu*mu;
        d_gmu[blockIdx.x] = mu;
        d_grs[blockIdx.x] = rsqrtf(var + 1e-5f);
    }
}

// ---------------- fused GN-apply + SiLU proj + time proj + mean add ----------------
__global__ void k_final(const float* __restrict__ gg, const float* __restrict__ gb,
                        const float* __restrict__ p2w, const float* __restrict__ p2b,
                        const float* __restrict__ p1w, const float* __restrict__ p1b,
                        float* __restrict__ out) {
    __shared__ float Xs[6144];
    __shared__ float Ss[LL];
    int bn = blockIdx.x;
    int b = bn / NN, n = bn % NN;
    int tid = threadIdx.x;   // 256
    for (int i = tid; i < 6144; i += 256) {
        int l = i >> 7, c = i & 127;
        int bl = b*LL + l, g = c >> 5;
        float v = d_gout[(size_t)n*12288 + bl*128 + c];
        Xs[i] = (v - d_gmu[bl*4+g]) * d_grs[bl*4+g] * gg[c] + gb[c];
    }
    __syncthreads();
    int lane = tid & 31, w = tid >> 5;
    for (int l = w*6; l < w*6+6; ++l) {
        float s = Xs[l*128+lane]*p2w[lane] + Xs[l*128+lane+32]*p2w[lane+32]
                + Xs[l*128+lane+64]*p2w[lane+64] + Xs[l*128+lane+96]*p2w[lane+96];
        #pragma unroll
        for (int o = 16; o; o >>= 1) s += __shfl_xor_sync(~0u, s, o);
        if (lane == 0) {
            float z = s + p2b[0];
            Ss[l] = z / (1.0f + expf(-z));
        }
    }
    __syncthreads();
    if (tid < L_OUT) {
        float acc = p1b[tid];
        #pragma unroll
        for (int l = 0; l < LL; ++l) acc += Ss[l] * p1w[tid*LL + l];
        out[((size_t)(b*L_OUT + tid))*NN + n] = acc + d_mean[bn];
    }
}

// ---------------- launcher ----------------
extern "C" void kernel_launch(void* const* d_in, const int* in_sizes, int n_in,
                              void* d_out, int out_size) {
    const float* x_enc   = (const float*)d_in[0];
    const float* adj     = (const float*)d_in[1];
    const float* pe_raw  = (const float*)d_in[2];
    const float* conv_w  = (const float*)d_in[3];
    const float* pos_w   = (const float*)d_in[4];
    const float* pos_b   = (const float*)d_in[5];
    const float* wq      = (const float*)d_in[6];
    const float* wk      = (const float*)d_in[7];
    const float* wv      = (const float*)d_in[8];
    const float* wo      = (const float*)d_in[9];
    const float* ln1_g   = (const float*)d_in[10];
    const float* ln1_b   = (const float*)d_in[11];
    const float* ff_w1   = (const float*)d_in[12];
    const float* ff_b1   = (const float*)d_in[13];
    const float* ff_w2   = (const float*)d_in[14];
    const float* ff_b2   = (const float*)d_in[15];
    const float* ln2_g   = (const float*)d_in[16];
    const float* ln2_b   = (const float*)d_in[17];
    const float* wpool   = (const float*)d_in[18];
    const float* gn_g    = (const float*)d_in[19];
    const float* gn_b    = (const float*)d_in[20];
    const float* p2_w    = (const float*)d_in[21];
    const float* p2_b    = (const float*)d_in[22];
    const float* p1_w    = (const float*)d_in[23];
    const float* p1_b    = (const float*)d_in[24];
    float* out = (float*)d_out;

    float *p_enc, *p_q, *p_k, *p_v, *p_agg, *p_pw;
    bf16 *p_hh, *p_hl, *p_qh, *p_ql, *p_ffh, *p_ffl, *p_adjh, *p_adjl;
    bf16 *p_Xh, *p_Xl, *p_peTh, *p_peTl, *p_WT2h, *p_WT2l, *p_pe2h, *p_pe2l, *p_wph, *p_wpl;
    cudaGetSymbolAddress((void**)&p_enc, d_enc);
    cudaGetSymbolAddress((void**)&p_q,   d_qb);
    cudaGetSymbolAddress((void**)&p_k,   d_kb);
    cudaGetSymbolAddress((void**)&p_v,   d_vb);
    cudaGetSymbolAddress((void**)&p_agg, d_agg);
    cudaGetSymbolAddress((void**)&p_pw,  d_pw);
    cudaGetSymbolAddress((void**)&p_hh,  d_hh);
    cudaGetSymbolAddress((void**)&p_hl,  d_hl);
    cudaGetSymbolAddress((void**)&p_qh,  d_qh);
    cudaGetSymbolAddress((void**)&p_ql,  d_ql);
    cudaGetSymbolAddress((void**)&p_ffh, d_ffh);
    cudaGetSymbolAddress((void**)&p_ffl, d_ffl);
    cudaGetSymbolAddress((void**)&p_adjh, d_adjh);
    cudaGetSymbolAddress((void**)&p_adjl, d_adjl);
    cudaGetSymbolAddress((void**)&p_Xh,  d_Xh);
    cudaGetSymbolAddress((void**)&p_Xl,  d_Xl);
    cudaGetSymbolAddress((void**)&p_peTh, d_peTh);
    cudaGetSymbolAddress((void**)&p_peTl, d_peTl);
    cudaGetSymbolAddress((void**)&p_WT2h, d_WT2h);
    cudaGetSymbolAddress((void**)&p_WT2l, d_WT2l);
    cudaGetSymbolAddress((void**)&p_pe2h, d_pe2h);
    cudaGetSymbolAddress((void**)&p_pe2l, d_pe2l);
    cudaGetSymbolAddress((void**)&p_wph, d_wph);
    cudaGetSymbolAddress((void**)&p_wpl, d_wpl);

    cudaFuncSetAttribute(k_attn,    cudaFuncAttributeMaxDynamicSharedMemorySize, ATTN_SMEM);
    cudaFuncSetAttribute(k_grouped, cudaFuncAttributeMaxDynamicSharedMemorySize, GRP_SMEM);
    cudaFuncSetAttribute(tgemm,     cudaFuncAttributeMaxDynamicSharedMemorySize, TG_SMEM);

    // prep + splits
    k_mean<<<(BNN+255)/256, 256>>>(x_enc);
    k_peT<<<(DD*NN+255)/256, 256>>>(pe_raw, pos_w, pos_b);
    k_WT2<<<(DD*DD*DD+255)/256, 256>>>(wpool);
    k_conv<<<BNN, 128>>>(x_enc, conv_w);
    k_split<<<(NN*NN+255)/256, 256>>>(adj, p_adjh, p_adjl, NN*NN);
    k_split<<<64, 256>>>(wq,    p_wph+WPO_Q,  p_wpl+WPO_Q,  16384);
    k_split<<<64, 256>>>(wk,    p_wph+WPO_K,  p_wpl+WPO_K,  16384);
    k_split<<<64, 256>>>(wv,    p_wph+WPO_V,  p_wpl+WPO_V,  16384);
    k_split<<<64, 256>>>(wo,    p_wph+WPO_O,  p_wpl+WPO_O,  16384);
    k_split<<<256, 256>>>(ff_w1, p_wph+WPO_F1, p_wpl+WPO_F1, 65536);
    k_split<<<256, 256>>>(ff_w2, p_wph+WPO_F2, p_wpl+WPO_F2, 65536);

    // temporal transformer
    k_ln<<<ROWS/8, 256>>>(p_enc, ln1_g, ln1_b);
    tgemm<<<dim3(1, ROWS/128), 256, TG_SMEM>>>(p_hh, p_hl, p_wph+WPO_Q, p_wpl+WPO_Q,
                                               p_q, nullptr, nullptr, ROWS, 128, 128, nullptr, 0);
    tgemm<<<dim3(1, ROWS/128), 256, TG_SMEM>>>(p_hh, p_hl, p_wph+WPO_K, p_wpl+WPO_K,
                                               p_k, nullptr, nullptr, ROWS, 128, 128, nullptr, 0);
    tgemm<<<dim3(1, ROWS/128), 256, TG_SMEM>>>(p_hh, p_hl, p_wph+WPO_V, p_wpl+WPO_V,
                                               p_v, nullptr, nullptr, ROWS, 128, 128, nullptr, 0);
    k_attn<<<BNN, 256, ATTN_SMEM>>>();
    tgemm<<<dim3(1, ROWS/128), 256, TG_SMEM>>>(p_qh, p_ql, p_wph+WPO_O, p_wpl+WPO_O,
                                               p_enc, nullptr, nullptr, ROWS, 128, 128, nullptr, 3);
    k_ln<<<ROWS/8, 256>>>(p_enc, ln2_g, ln2_b);
    tgemm<<<dim3(4, ROWS/128), 256, TG_SMEM>>>(p_hh, p_hl, p_wph+WPO_F1, p_wpl+WPO_F1,
                                               nullptr, p_ffh, p_ffl, ROWS, 512, 128, ff_b1, 2);
    tgemm<<<dim3(1, ROWS/128), 256, TG_SMEM>>>(p_ffh, p_ffl, p_wph+WPO_F2, p_wpl+WPO_F2,
                                               p_enc, nullptr, nullptr, ROWS, 128, 512, ff_b2, 3);

    // spatial GCN
    k_transpose<<<dim3(94, BLL), 256>>>();
    tgemm<<<dim3(1,   24), 256, TG_SMEM>>>(p_adjh, p_adjl, p_peTh, p_peTl,
                                           nullptr, p_pe2h, p_pe2l, NN, 128, NN, nullptr, 5);
    tgemm<<<dim3(128, 24), 256, TG_SMEM>>>(p_pe2h, p_pe2l, p_WT2h, p_WT2l,
                                           p_pw, nullptr, nullptr, NN, 16384, 128, nullptr, 0);
    tgemm<<<dim3(96,  24), 256, TG_SMEM>>>(p_adjh, p_adjl, p_Xh, p_Xl,
                                           p_agg, nullptr, nullptr, NN, 12288, NN, nullptr, 0);
    k_grouped<<<NN, 256, GRP_SMEM>>>();

    // groupnorm + head
    k_gnstats<<<BLL*4, 256>>>();
    k_final<<<BNN, 256>>>(gn_g, gn_b, p2_w, p2_b, p1_w, p1_b, out);
}

// round 6
// speedup vs baseline: 1.9841x; 1.1880x over previous
#include <cuda_runtime.h>
#include <cuda_bf16.h>
#include <math.h>
#include <stdint.h>

#define BB 2
#define LL 48
#define NN 3000
#define DD 128
#define L_OUT 24
#define BNN (BB*NN)          // 6000
#define BLL (BB*LL)          // 96
#define ROWS (BNN*LL)        // 288000 token rows
#define ENC_N (ROWS*DD)      // 36,864,000

typedef __nv_bfloat16 bf16;

// ---------------- scratch (device globals; no runtime allocation) ----------------
__device__ float d_mean[BNN];
__device__ float d_enc[ENC_N];           // enc[seq][l][c]
__device__ float d_qb[ENC_N];            // q fp32 (raw)
__device__ float d_kb[ENC_N];
__device__ float d_vb[ENC_N];
__device__ float d_gout[NN*BLL*DD];      // gout[n][bl][o]
__device__ float d_gmu[BLL*4];
__device__ float d_grs[BLL*4];

// bf16 split pairs
__device__ bf16 d_hh[ENC_N],  d_hl[ENC_N];     // LN output
__device__ bf16 d_qh[ENC_N],  d_ql[ENC_N];     // att_pre
__device__ bf16 d_ffh[ROWS*512], d_ffl[ROWS*512];
__device__ bf16 d_adjh[NN*NN], d_adjl[NN*NN];
__device__ bf16 d_Xh[BLL*DD*NN], d_Xl[BLL*DD*NN];
__device__ bf16 d_peTh[DD*NN], d_peTl[DD*NN];
__device__ bf16 d_WT2h[DD*DD*DD], d_WT2l[DD*DD*DD];  // [(o*128+i)][d]
__device__ bf16 d_pe2h[NN*DD], d_pe2l[NN*DD];
__device__ bf16 d_aggh[NN*BLL*DD], d_aggl[NN*BLL*DD]; // [n][bl*128+i]
__device__ bf16 d_pwh[NN*DD*DD], d_pwl[NN*DD*DD];     // [n][o*128+i]
// weight pool: [wq|wk|wv|wo|ffw1|ffw2] (contiguous QKV!)
#define WPO_Q 0
#define WPO_K 16384
#define WPO_V 32768
#define WPO_O 49152
#define WPO_F1 65536
#define WPO_F2 131072
__device__ bf16 d_wph[196608], d_wpl[196608];

__device__ __forceinline__ float gelu_exact(float x) {
    return 0.5f * x * (1.0f + erff(x * 0.70710678118654752f));
}
__device__ __forceinline__ void pack_split(float x0, float x1, uint32_t& hi, uint32_t& lo) {
    uint32_t h;
    asm("cvt.rn.bf16x2.f32 %0, %1, %2;" : "=r"(h) : "f"(x1), "f"(x0));
    float h0 = __uint_as_float(h << 16);
    float h1 = __uint_as_float(h & 0xFFFF0000u);
    float r0 = x0 - h0, r1 = x1 - h1;
    uint32_t l;
    asm("cvt.rn.bf16x2.f32 %0, %1, %2;" : "=r"(l) : "f"(r1), "f"(r0));
    hi = h; lo = l;
}
__device__ __forceinline__ void scalar_split(float v, bf16& h, bf16& l) {
    h = __float2bfloat16_rn(v);
    l = __float2bfloat16_rn(v - __bfloat162float(h));
}

// ---------------- small prep kernels ----------------
__global__ void k_mean(const float* __restrict__ x) {
    int i = blockIdx.x * blockDim.x + threadIdx.x;
    if (i >= BNN) return;
    int b = i / NN, n = i % NN;
    float s = 0.f;
    #pragma unroll
    for (int l = 0; l < LL; ++l) s += x[(b*LL + l)*NN + n];
    d_mean[i] = s * (1.0f / LL);
}

__global__ void k_split(const float* __restrict__ in, bf16* __restrict__ h,
                        bf16* __restrict__ l, int n) {
    int i = blockIdx.x * blockDim.x + threadIdx.x;
    if (i >= n) return;
    scalar_split(in[i], h[i], l[i]);
}

__global__ void k_peT(const float* __restrict__ pr, const float* __restrict__ pw,
                      const float* __restrict__ pb) {
    int i = blockIdx.x * blockDim.x + threadIdx.x;
    if (i >= DD*NN) return;
    int d = i / NN, n = i % NN;
    float v = pr[n]*pw[d*3] + pr[NN+n]*pw[d*3+1] + pr[2*NN+n]*pw[d*3+2] + pb[d];
    scalar_split(v, d_peTh[i], d_peTl[i]);
}

// WT2[(o*128+i)][d] = wp[(d*128+i)][o]  -> pw GEMM outputs pw[n][o][i] (mma B layout)
__global__ void k_WT2(const float* __restrict__ wp) {
    int idx = blockIdx.x * blockDim.x + threadIdx.x;
    if (idx >= DD*DD*DD) return;
    int d = idx & 127;
    int nrow = idx >> 7;          // o*128+i
    int i = nrow & 127, o = nrow >> 7;
    scalar_split(wp[(d*128 + i)*128 + o], d_WT2h[idx], d_WT2l[idx]);
}

// circular conv1d k=3: enc[seq][l][c]
__global__ void k_conv(const float* __restrict__ x, const float* __restrict__ cw) {
    __shared__ float xs[LL + 2];
    int seq = blockIdx.x;
    int b = seq / NN, n = seq % NN;
    float m = d_mean[seq];
    int t = threadIdx.x;   // 128
    if (t < LL) xs[t + 1] = x[(b*LL + t)*NN + n] - m;
    __syncthreads();
    if (t == 0) { xs[0] = xs[LL]; xs[LL+1] = xs[1]; }
    __syncthreads();
    float w0 = cw[t*3], w1 = cw[t*3+1], w2 = cw[t*3+2];
    float* out = d_enc + (size_t)seq * (LL*DD);
    #pragma unroll
    for (int l = 0; l < LL; ++l)
        out[l*DD + t] = w0*xs[l] + w1*xs[l+1] + w2*xs[l+2];
}

// LayerNorm over rows of 128 (one warp per row), writes split bf16 pair
__global__ void k_ln(const float* __restrict__ X,
                     const float* __restrict__ g, const float* __restrict__ bta) {
    int warp = (blockIdx.x * blockDim.x + threadIdx.x) >> 5;
    int lane = threadIdx.x & 31;
    const float* xr = X + (size_t)warp * DD;
    float4 v = *(const float4*)(xr + lane*4);
    float s = v.x + v.y + v.z + v.w;
    float sq = v.x*v.x + v.y*v.y + v.z*v.z + v.w*v.w;
    #pragma unroll
    for (int o = 16; o; o >>= 1) {
        s  += __shfl_xor_sync(~0u, s, o);
        sq += __shfl_xor_sync(~0u, sq, o);
    }
    float mu = s * (1.0f/DD);
    float var = sq * (1.0f/DD) - mu*mu;
    float rs = rsqrtf(var + 1e-5f);
    float4 gg = *(const float4*)(g + lane*4);
    float4 bb = *(const float4*)(bta + lane*4);
    float o0 = (v.x - mu)*rs*gg.x + bb.x;
    float o1 = (v.y - mu)*rs*gg.y + bb.y;
    float o2 = (v.z - mu)*rs*gg.z + bb.z;
    float o3 = (v.w - mu)*rs*gg.w + bb.w;
    uint32_t h01, l01, h23, l23;
    pack_split(o0, o1, h01, l01);
    pack_split(o2, o3, h23, l23);
    ((uint2*)d_hh)[(size_t)warp*32 + lane] = make_uint2(h01, h23);
    ((uint2*)d_hl)[(size_t)warp*32 + lane] = make_uint2(l01, l23);
}

// ---------------- per-sequence linear attention: (softmax_q @ softmax_k^T) @ v ----------------
#define SPAD 52
#define ATTN_SMEM ((6144*3 + LL*SPAD) * 4)    // 83712 B -> 2 CTAs/SM
__global__ void __launch_bounds__(256) k_attn() {
    extern __shared__ float sm[];
    float* Q  = sm;               // 48x128
    float* KK = sm + 6144;        // 48x128
    float* V  = sm + 12288;       // 48x128
    float* S  = sm + 18432;       // 48xSPAD
    int seq = blockIdx.x, tid = threadIdx.x;
    size_t base = (size_t)seq * 6144;
    for (int i = tid; i < 6144; i += 256) {
        Q[i] = d_qb[base+i]; KK[i] = d_kb[base+i]; V[i] = d_vb[base+i];
    }
    __syncthreads();
    int te = tid & 31, tg = tid >> 5;
    // Q row softmax * d^-0.5
    for (int l = tg*6; l < tg*6+6; ++l) {
        float4 v = *(float4*)&Q[l*128 + te*4];
        float mx = fmaxf(fmaxf(v.x, v.y), fmaxf(v.z, v.w));
        #pragma unroll
        for (int o = 16; o; o >>= 1) mx = fmaxf(mx, __shfl_xor_sync(~0u, mx, o));
        v.x = expf(v.x - mx); v.y = expf(v.y - mx);
        v.z = expf(v.z - mx); v.w = expf(v.w - mx);
        float s = v.x + v.y + v.z + v.w;
        #pragma unroll
        for (int o = 16; o; o >>= 1) s += __shfl_xor_sync(~0u, s, o);
        float f = 0.08838834764831845f / s;
        v.x *= f; v.y *= f; v.z *= f; v.w *= f;
        *(float4*)&Q[l*128 + te*4] = v;
    }
    // K col softmax over L
    if (tid < 128) {
        int c = tid;
        float mx = -1e30f;
        #pragma unroll
        for (int l = 0; l < LL; ++l) mx = fmaxf(mx, KK[l*128 + c]);
        float s = 0.f;
        float ev[LL];
        #pragma unroll
        for (int l = 0; l < LL; ++l) { ev[l] = expf(KK[l*128 + c] - mx); s += ev[l]; }
        float inv = 1.0f / s;
        #pragma unroll
        for (int l = 0; l < LL; ++l) KK[l*128 + c] = ev[l] * inv;
    }
    __syncthreads();
    // S[i][j] = sum_d Q[i][d]*KK[j][d]   (48x48, k=128)
    {
        int ty = tid >> 4, tx = tid & 15;       // 16x16 threads, 3x3 outputs each
        int i0 = ty*3, j0 = tx*3;
        float a[3][3] = {};
        #pragma unroll
        for (int d4 = 0; d4 < 128; d4 += 4) {
            float4 q0 = *(float4*)&Q [(i0+0)*128 + d4];
            float4 q1 = *(float4*)&Q [(i0+1)*128 + d4];
            float4 q2 = *(float4*)&Q [(i0+2)*128 + d4];
            float4 k0 = *(float4*)&KK[(j0+0)*128 + d4];
            float4 k1 = *(float4*)&KK[(j0+1)*128 + d4];
            float4 k2 = *(float4*)&KK[(j0+2)*128 + d4];
            a[0][0] += q0.x*k0.x + q0.y*k0.y + q0.z*k0.z + q0.w*k0.w;
            a[0][1] += q0.x*k1.x + q0.y*k1.y + q0.z*k1.z + q0.w*k1.w;
            a[0][2] += q0.x*k2.x + q0.y*k2.y + q0.z*k2.z + q0.w*k2.w;
            a[1][0] += q1.x*k0.x + q1.y*k0.y + q1.z*k0.z + q1.w*k0.w;
            a[1][1] += q1.x*k1.x + q1.y*k1.y + q1.z*k1.z + q1.w*k1.w;
            a[1][2] += q1.x*k2.x + q1.y*k2.y + q1.z*k2.z + q1.w*k2.w;
            a[2][0] += q2.x*k0.x + q2.y*k0.y + q2.z*k0.z + q2.w*k0.w;
            a[2][1] += q2.x*k1.x + q2.y*k1.y + q2.z*k1.z + q2.w*k1.w;
            a[2][2] += q2.x*k2.x + q2.y*k2.y + q2.z*k2.z + q2.w*k2.w;
        }
        #pragma unroll
        for (int r = 0; r < 3; ++r)
            #pragma unroll
            for (int c = 0; c < 3; ++c)
                S[(i0+r)*SPAD + j0 + c] = a[r][c];
    }
    __syncthreads();
    // att[l][e] = sum_j S[l][j]*V[j][e]  -> split store to d_qh/d_ql
    {
        int ty = tid >> 4, tx = tid & 15;       // 3 l-rows x 8 e-cols per thread
        int l0 = ty*3, e0 = tx*8;
        float a[3][8] = {};
        #pragma unroll
        for (int j = 0; j < LL; ++j) {
            float s0 = S[(l0+0)*SPAD + j];
            float s1 = S[(l0+1)*SPAD + j];
            float s2 = S[(l0+2)*SPAD + j];
            float4 v0 = *(float4*)&V[j*128 + e0];
            float4 v1 = *(float4*)&V[j*128 + e0 + 4];
            a[0][0]+=s0*v0.x; a[0][1]+=s0*v0.y; a[0][2]+=s0*v0.z; a[0][3]+=s0*v0.w;
            a[0][4]+=s0*v1.x; a[0][5]+=s0*v1.y; a[0][6]+=s0*v1.z; a[0][7]+=s0*v1.w;
            a[1][0]+=s1*v0.x; a[1][1]+=s1*v0.y; a[1][2]+=s1*v0.z; a[1][3]+=s1*v0.w;
            a[1][4]+=s1*v1.x; a[1][5]+=s1*v1.y; a[1][6]+=s1*v1.z; a[1][7]+=s1*v1.w;
            a[2][0]+=s2*v0.x; a[2][1]+=s2*v0.y; a[2][2]+=s2*v0.z; a[2][3]+=s2*v0.w;
            a[2][4]+=s2*v1.x; a[2][5]+=s2*v1.y; a[2][6]+=s2*v1.z; a[2][7]+=s2*v1.w;
        }
        #pragma unroll
        for (int r = 0; r < 3; ++r) {
            #pragma unroll
            for (int c = 0; c < 8; c += 2) {
                uint32_t hp, lp;
                pack_split(a[r][c], a[r][c+1], hp, lp);
                size_t w2 = (base + (size_t)(l0+r)*128 + e0 + c) >> 1;
                ((uint32_t*)d_qh)[w2] = hp;
                ((uint32_t*)d_ql)[w2] = lp;
            }
        }
    }
}

// ---------------- 3x-bf16 split GEMM with pre-split inputs ----------------
// epi: 0 store fp32 C; 2 gelu(+bias)->Oh/Ol; 3 C+= ; 5 ->Oh/Ol; 6 QKV route C/C2/C3
#define TGW 12
#define TG_SMEM (2*4*128*TGW*4)   // 49152 bytes
__global__ void __launch_bounds__(256) tgemm(
    const bf16* __restrict__ Ah, const bf16* __restrict__ Al,
    const bf16* __restrict__ Bh, const bf16* __restrict__ Bl,
    float* __restrict__ C, float* __restrict__ C2, float* __restrict__ C3,
    bf16* __restrict__ Oh, bf16* __restrict__ Ol,
    int M, int N, int K, const float* __restrict__ bias, int epi, int gswap)
{
    extern __shared__ uint32_t SMu[];
    const int tid = threadIdx.x;
    const int m0 = (gswap ? blockIdx.x : blockIdx.y) * 128;
    const int n0 = (gswap ? blockIdx.y : blockIdx.x) * 128;
    const int lrow = tid >> 1, comp = tid & 1;
    const int warp = tid >> 5, lane = tid & 31;
    const int wm = (warp >> 2) * 64, wn = (warp & 3) * 32;
    const int g = lane >> 2, tig = lane & 3;

    const bf16* Arow = (comp ? Al : Ah) + (size_t)(m0 + lrow) * K;
    const bf16* Brow = (comp ? Bl : Bh) + (size_t)(n0 + lrow) * K;
    const bool mok = (m0 + lrow) < M;

    float acc[4][4][4];
    #pragma unroll
    for (int a = 0; a < 4; ++a)
        #pragma unroll
        for (int b = 0; b < 4; ++b)
            #pragma unroll
            for (int c = 0; c < 4; ++c) acc[a][b][c] = 0.f;

    const int nk = (K + 15) / 16;
    uint4 pa0, pa1, pb0, pb1;
    const uint4 zz = make_uint4(0,0,0,0);

    #define FETCH(kt) do { \
        int k_ = (kt)*16; \
        pa0 = (mok && k_+8  <= K) ? *(const uint4*)(Arow + k_    ) : zz; \
        pa1 = (mok && k_+16 <= K) ? *(const uint4*)(Arow + k_ + 8) : zz; \
        pb0 = (k_+8  <= K) ? *(const uint4*)(Brow + k_    ) : zz; \
        pb1 = (k_+16 <= K) ? *(const uint4*)(Brow + k_ + 8) : zz; \
    } while (0)
    #define STORE(buf) do { \
        uint32_t* pA = SMu + (((buf)*4 + comp)*128 + lrow)*TGW; \
        pA[0]=pa0.x; pA[1]=pa0.y; pA[2]=pa0.z; pA[3]=pa0.w; \
        pA[4]=pa1.x; pA[5]=pa1.y; pA[6]=pa1.z; pA[7]=pa1.w; \
        uint32_t* pB = SMu + (((buf)*4 + 2 + comp)*128 + lrow)*TGW; \
        pB[0]=pb0.x; pB[1]=pb0.y; pB[2]=pb0.z; pB[3]=pb0.w; \
        pB[4]=pb1.x; pB[5]=pb1.y; pB[6]=pb1.z; pB[7]=pb1.w; \
    } while (0)

    FETCH(0); STORE(0);
    __syncthreads();

    int s = 0;
    for (int kt = 0; kt < nk; ++kt) {
        bool nxt = (kt + 1) < nk;
        if (nxt) FETCH(kt + 1);

        uint32_t ah[4][4], al[4][4], bh[4][2], bl[4][2];
        const uint32_t* Ah_s = SMu + ((s*4 + 0)*128)*TGW;
        const uint32_t* Al_s = SMu + ((s*4 + 1)*128)*TGW;
        const uint32_t* Bh_s = SMu + ((s*4 + 2)*128)*TGW;
        const uint32_t* Bl_s = SMu + ((s*4 + 3)*128)*TGW;
        #pragma unroll
        for (int mi = 0; mi < 4; ++mi) {
            int r = wm + mi*16 + g;
            ah[mi][0] = Ah_s[ r     *TGW + tig    ];
            ah[mi][1] = Ah_s[(r + 8)*TGW + tig    ];
            ah[mi][2] = Ah_s[ r     *TGW + tig + 4];
            ah[mi][3] = Ah_s[(r + 8)*TGW + tig + 4];
            al[mi][0] = Al_s[ r     *TGW + tig    ];
            al[mi][1] = Al_s[(r + 8)*TGW + tig    ];
            al[mi][2] = Al_s[ r     *TGW + tig + 4];
            al[mi][3] = Al_s[(r + 8)*TGW + tig + 4];
        }
        #pragma unroll
        for (int ni = 0; ni < 4; ++ni) {
            int r = wn + ni*8 + g;
            bh[ni][0] = Bh_s[r*TGW + tig    ];
            bh[ni][1] = Bh_s[r*TGW + tig + 4];
            bl[ni][0] = Bl_s[r*TGW + tig    ];
            bl[ni][1] = Bl_s[r*TGW + tig + 4];
        }
        #pragma unroll
        for (int mi = 0; mi < 4; ++mi)
            #pragma unroll
            for (int ni = 0; ni < 4; ++ni) {
                asm volatile(
                    "mma.sync.aligned.m16n8k16.row.col.f32.bf16.bf16.f32 "
                    "{%0,%1,%2,%3}, {%4,%5,%6,%7}, {%8,%9}, {%0,%1,%2,%3};"
                    : "+f"(acc[mi][ni][0]), "+f"(acc[mi][ni][1]),
                      "+f"(acc[mi][ni][2]), "+f"(acc[mi][ni][3])
                    : "r"(ah[mi][0]), "r"(ah[mi][1]), "r"(ah[mi][2]), "r"(ah[mi][3]),
                      "r"(bl[ni][0]), "r"(bl[ni][1]));
                asm volatile(
                    "mma.sync.aligned.m16n8k16.row.col.f32.bf16.bf16.f32 "
                    "{%0,%1,%2,%3}, {%4,%5,%6,%7}, {%8,%9}, {%0,%1,%2,%3};"
                    : "+f"(acc[mi][ni][0]), "+f"(acc[mi][ni][1]),
                      "+f"(acc[mi][ni][2]), "+f"(acc[mi][ni][3])
                    : "r"(al[mi][0]), "r"(al[mi][1]), "r"(al[mi][2]), "r"(al[mi][3]),
                      "r"(bh[ni][0]), "r"(bh[ni][1]));
                asm volatile(
                    "mma.sync.aligned.m16n8k16.row.col.f32.bf16.bf16.f32 "
                    "{%0,%1,%2,%3}, {%4,%5,%6,%7}, {%8,%9}, {%0,%1,%2,%3};"
                    : "+f"(acc[mi][ni][0]), "+f"(acc[mi][ni][1]),
                      "+f"(acc[mi][ni][2]), "+f"(acc[mi][ni][3])
                    : "r"(ah[mi][0]), "r"(ah[mi][1]), "r"(ah[mi][2]), "r"(ah[mi][3]),
                      "r"(bh[ni][0]), "r"(bh[ni][1]));
            }
        if (nxt) STORE(s ^ 1);
        __syncthreads();
        s ^= 1;
    }
    #undef FETCH
    #undef STORE

    // epilogue
    #pragma unroll
    for (int mi = 0; mi < 4; ++mi) {
        #pragma unroll
        for (int ni = 0; ni < 4; ++ni) {
            int n = n0 + wn + ni*8 + tig*2;
            float bv0 = 0.f, bv1 = 0.f;
            if (bias) { bv0 = bias[n]; bv1 = bias[n+1]; }
            #pragma unroll
            for (int half = 0; half < 2; ++half) {
                int m = m0 + wm + mi*16 + g + half*8;
                if (m >= M) continue;
                float r0 = acc[mi][ni][half*2+0] + bv0;
                float r1 = acc[mi][ni][half*2+1] + bv1;
                size_t off = (size_t)m * N + n;
                if (epi == 0) {
                    *(float2*)(C + off) = make_float2(r0, r1);
                } else if (epi == 2) {
                    r0 = gelu_exact(r0); r1 = gelu_exact(r1);
                    uint32_t hp, lp;
                    pack_split(r0, r1, hp, lp);
                    ((uint32_t*)Oh)[off >> 1] = hp;
                    ((uint32_t*)Ol)[off >> 1] = lp;
                } else if (epi == 3) {
                    float2 cur = *(float2*)(C + off);
                    *(float2*)(C + off) = make_float2(r0 + cur.x, r1 + cur.y);
                } else if (epi == 5) {
                    uint32_t hp, lp;
                    pack_split(r0, r1, hp, lp);
                    ((uint32_t*)Oh)[off >> 1] = hp;
                    ((uint32_t*)Ol)[off >> 1] = lp;
                } else { // 6: QKV routing, each target row-stride 128
                    int buf = n >> 7, col = n & 127;
                    float* Cd = (buf == 0) ? C : (buf == 1 ? C2 : C3);
                    *(float2*)(Cd + ((size_t)m << 7) + col) = make_float2(r0, r1);
                }
            }
        }
    }
}

// ---------------- transpose enc -> X[(bl*128+d)][n], split bf16 out ----------------
__global__ void k_transpose() {   // grid (94, 96), 256 threads
    __shared__ float T[32*129];
    int n0 = blockIdx.x * 32;
    int bl = blockIdx.y;
    int b = bl / LL, l = bl % LL;
    int tid = threadIdx.x;
    int nrem = NN - n0; if (nrem > 32) nrem = 32;
    for (int i = tid; i < 32*128; i += 256) {
        int r = i >> 7, c = i & 127;
        if (r < nrem)
            T[r*129 + c] = d_enc[((size_t)(b*NN + n0 + r))*6144 + l*128 + c];
    }
    __syncthreads();
    for (int i = tid; i < 128*32; i += 256) {
        int dd = i >> 5, j = i & 31;
        if (j < nrem) {
            float v = T[j*129 + dd];
            size_t o = ((size_t)(bl*128 + dd))*NN + n0 + j;
            scalar_split(v, d_Xh[o], d_Xl[o]);
        }
    }
}

// ---------------- tensorized per-node grouped GEMM ----------------
// gout[n] (96x128) = agg[n](96x128,k=i) @ pw[n]^T (B rows = o, k = i)
#define SA 68   // uint32 row stride
#define GRP2_SMEM ((2*96*SA + 2*128*SA) * 4)   // 121856 B
__global__ void __launch_bounds__(256) k_grouped2() {
    extern __shared__ uint32_t SMu[];
    uint32_t* Ah_s = SMu;                 // agg hi: 96 x SA
    uint32_t* Al_s = SMu + 96*SA;
    uint32_t* Bh_s = SMu + 2*96*SA;       // pw hi: 128 x SA
    uint32_t* Bl_s = SMu + 2*96*SA + 128*SA;
    int node = blockIdx.x, tid = threadIdx.x;
    const uint4* agh = (const uint4*)(d_aggh + (size_t)node * 12288);
    const uint4* agl = (const uint4*)(d_aggl + (size_t)node * 12288);
    const uint4* pwh = (const uint4*)(d_pwh + (size_t)node * 16384);
    const uint4* pwl = (const uint4*)(d_pwl + (size_t)node * 16384);
    // stage A (96 rows x 16 uint4) and B (128 rows x 16 uint4)
    for (int i = tid; i < 1536; i += 256) {
        int r = i >> 4, c = (i & 15) * 4;
        *(uint4*)(Ah_s + r*SA + c) = agh[i];
        *(uint4*)(Al_s + r*SA + c) = agl[i];
    }
    for (int i = tid; i < 2048; i += 256) {
        int r = i >> 4, c = (i & 15) * 4;
        *(uint4*)(Bh_s + r*SA + c) = pwh[i];
        *(uint4*)(Bl_s + r*SA + c) = pwl[i];
    }
    __syncthreads();

    int warp = tid >> 5, lane = tid & 31;
    int wm = (warp >> 2) * 48, wn = (warp & 3) * 32;
    int g = lane >> 2, tig = lane & 3;
    float acc[3][4][4];
    #pragma unroll
    for (int a = 0; a < 3; ++a)
        #pragma unroll
        for (int b = 0; b < 4; ++b)
            #pragma unroll
            for (int c = 0; c < 4; ++c) acc[a][b][c] = 0.f;

    #pragma unroll
    for (int kt = 0; kt < 8; ++kt) {
        uint32_t ah[3][4], al[3][4], bh[4][2], bl[4][2];
        int kb = kt*8 + tig;
        #pragma unroll
        for (int mi = 0; mi < 3; ++mi) {
            int r = wm + mi*16 + g;
            ah[mi][0] = Ah_s[ r     *SA + kb    ];
            ah[mi][1] = Ah_s[(r + 8)*SA + kb    ];
            ah[mi][2] = Ah_s[ r     *SA + kb + 4];
            ah[mi][3] = Ah_s[(r + 8)*SA + kb + 4];
            al[mi][0] = Al_s[ r     *SA + kb    ];
            al[mi][1] = Al_s[(r + 8)*SA + kb    ];
            al[mi][2] = Al_s[ r     *SA + kb + 4];
            al[mi][3] = Al_s[(r + 8)*SA + kb + 4];
        }
        #pragma unroll
        for (int ni = 0; ni < 4; ++ni) {
            int r = wn + ni*8 + g;
            bh[ni][0] = Bh_s[r*SA + kb    ];
            bh[ni][1] = Bh_s[r*SA + kb + 4];
            bl[ni][0] = Bl_s[r*SA + kb    ];
            bl[ni][1] = Bl_s[r*SA + kb + 4];
        }
        #pragma unroll
        for (int mi = 0; mi < 3; ++mi)
            #pragma unroll
            for (int ni = 0; ni < 4; ++ni) {
                asm volatile(
                    "mma.sync.aligned.m16n8k16.row.col.f32.bf16.bf16.f32 "
                    "{%0,%1,%2,%3}, {%4,%5,%6,%7}, {%8,%9}, {%0,%1,%2,%3};"
                    : "+f"(acc[mi][ni][0]), "+f"(acc[mi][ni][1]),
                      "+f"(acc[mi][ni][2]), "+f"(acc[mi][ni][3])
                    : "r"(ah[mi][0]), "r"(ah[mi][1]), "r"(ah[mi][2]), "r"(ah[mi][3]),
                      "r"(bl[ni][0]), "r"(bl[ni][1]));
                asm volatile(
                    "mma.sync.aligned.m16n8k16.row.col.f32.bf16.bf16.f32 "
                    "{%0,%1,%2,%3}, {%4,%5,%6,%7}, {%8,%9}, {%0,%1,%2,%3};"
                    : "+f"(acc[mi][ni][0]), "+f"(acc[mi][ni][1]),
                      "+f"(acc[mi][ni][2]), "+f"(acc[mi][ni][3])
                    : "r"(al[mi][0]), "r"(al[mi][1]), "r"(al[mi][2]), "r"(al[mi][3]),
                      "r"(bh[ni][0]), "r"(bh[ni][1]));
                asm volatile(
                    "mma.sync.aligned.m16n8k16.row.col.f32.bf16.bf16.f32 "
                    "{%0,%1,%2,%3}, {%4,%5,%6,%7}, {%8,%9}, {%0,%1,%2,%3};"
                    : "+f"(acc[mi][ni][0]), "+f"(acc[mi][ni][1]),
                      "+f"(acc[mi][ni][2]), "+f"(acc[mi][ni][3])
                    : "r"(ah[mi][0]), "r"(ah[mi][1]), "r"(ah[mi][2]), "r"(ah[mi][3]),
                      "r"(bh[ni][0]), "r"(bh[ni][1]));
            }
    }

    float* outp = d_gout + (size_t)node * 12288;
    #pragma unroll
    for (int mi = 0; mi < 3; ++mi)
        #pragma unroll
        for (int ni = 0; ni < 4; ++ni) {
            int n = wn + ni*8 + tig*2;
            #pragma unroll
            for (int half = 0; half < 2; ++half) {
                int m = wm + mi*16 + g + half*8;
                *(float2*)(outp + m*128 + n) =
                    make_float2(acc[mi][ni][half*2+0], acc[mi][ni][half*2+1]);
            }
        }
}

// ---------------- GroupNorm stats per (bl, group) ----------------
__global__ void k_gnstats() {   // grid BLL*4
    __shared__ float rs[256], rq[256];
    int bl = blockIdx.x >> 2, g = blockIdx.x & 3;
    int tid = threadIdx.x;
    float s = 0.f, q = 0.f;
    for (int i = tid; i < NN*32; i += 256) {
        int n = i >> 5, o = i & 31;
        float v = d_gout[(size_t)n*12288 + bl*128 + g*32 + o];
        s += v; q += v*v;
    }
    rs[tid] = s; rq[tid] = q;
    __syncthreads();
    for (int st = 128; st; st >>= 1) {
        if (tid < st) { rs[tid] += rs[tid+st]; rq[tid] += rq[tid+st]; }
        __syncthreads();
    }
    if (tid == 0) {
        const float inv = 1.0f / (float)(NN*32);
        float mu = rs[0] * inv;
        float var = rq[0] * inv - mu*mu;
        d_gmu[blockIdx.x] = mu;
        d_grs[blockIdx.x] = rsqrtf(var + 1e-5f);
    }
}

// ---------------- fused GN-apply + SiLU proj + time proj + mean add ----------------
__global__ void k_final(const float* __restrict__ gg, const float* __restrict__ gb,
                        const float* __restrict__ p2w, const float* __restrict__ p2b,
                        const float* __restrict__ p1w, const float* __restrict__ p1b,
                        float* __restrict__ out) {
    __shared__ float Xs[6144];
    __shared__ float Ss[LL];
    int bn = blockIdx.x;
    int b = bn / NN, n = bn % NN;
    int tid = threadIdx.x;   // 256
    for (int i = tid; i < 6144; i += 256) {
        int l = i >> 7, c = i & 127;
        int bl = b*LL + l, g = c >> 5;
        float v = d_gout[(size_t)n*12288 + bl*128 + c];
        Xs[i] = (v - d_gmu[bl*4+g]) * d_grs[bl*4+g] * gg[c] + gb[c];
    }
    __syncthreads();
    int lane = tid & 31, w = tid >> 5;
    for (int l = w*6; l < w*6+6; ++l) {
        float s = Xs[l*128+lane]*p2w[lane] + Xs[l*128+lane+32]*p2w[lane+32]
                + Xs[l*128+lane+64]*p2w[lane+64] + Xs[l*128+lane+96]*p2w[lane+96];
        #pragma unroll
        for (int o = 16; o; o >>= 1) s += __shfl_xor_sync(~0u, s, o);
        if (lane == 0) {
            float z = s + p2b[0];
            Ss[l] = z / (1.0f + expf(-z));
        }
    }
    __syncthreads();
    if (tid < L_OUT) {
        float acc = p1b[tid];
        #pragma unroll
        for (int l = 0; l < LL; ++l) acc += Ss[l] * p1w[tid*LL + l];
        out[((size_t)(b*L_OUT + tid))*NN + n] = acc + d_mean[bn];
    }
}

// ---------------- launcher ----------------
extern "C" void kernel_launch(void* const* d_in, const int* in_sizes, int n_in,
                              void* d_out, int out_size) {
    const float* x_enc   = (const float*)d_in[0];
    const float* adj     = (const float*)d_in[1];
    const float* pe_raw  = (const float*)d_in[2];
    const float* conv_w  = (const float*)d_in[3];
    const float* pos_w   = (const float*)d_in[4];
    const float* pos_b   = (const float*)d_in[5];
    const float* wq      = (const float*)d_in[6];
    const float* wk      = (const float*)d_in[7];
    const float* wv      = (const float*)d_in[8];
    const float* wo      = (const float*)d_in[9];
    const float* ln1_g   = (const float*)d_in[10];
    const float* ln1_b   = (const float*)d_in[11];
    const float* ff_w1   = (const float*)d_in[12];
    const float* ff_b1   = (const float*)d_in[13];
    const float* ff_w2   = (const float*)d_in[14];
    const float* ff_b2   = (const float*)d_in[15];
    const float* ln2_g   = (const float*)d_in[16];
    const float* ln2_b   = (const float*)d_in[17];
    const float* wpool   = (const float*)d_in[18];
    const float* gn_g    = (const float*)d_in[19];
    const float* gn_b    = (const float*)d_in[20];
    const float* p2_w    = (const float*)d_in[21];
    const float* p2_b    = (const float*)d_in[22];
    const float* p1_w    = (const float*)d_in[23];
    const float* p1_b    = (const float*)d_in[24];
    float* out = (float*)d_out;

    float *p_enc, *p_q, *p_k, *p_v;
    bf16 *p_hh, *p_hl, *p_qh, *p_ql, *p_ffh, *p_ffl, *p_adjh, *p_adjl;
    bf16 *p_Xh, *p_Xl, *p_peTh, *p_peTl, *p_WT2h, *p_WT2l, *p_pe2h, *p_pe2l;
    bf16 *p_aggh, *p_aggl, *p_pwh, *p_pwl, *p_wph, *p_wpl;
    cudaGetSymbolAddress((void**)&p_enc, d_enc);
    cudaGetSymbolAddress((void**)&p_q,   d_qb);
    cudaGetSymbolAddress((void**)&p_k,   d_kb);
    cudaGetSymbolAddress((void**)&p_v,   d_vb);
    cudaGetSymbolAddress((void**)&p_hh,  d_hh);
    cudaGetSymbolAddress((void**)&p_hl,  d_hl);
    cudaGetSymbolAddress((void**)&p_qh,  d_qh);
    cudaGetSymbolAddress((void**)&p_ql,  d_ql);
    cudaGetSymbolAddress((void**)&p_ffh, d_ffh);
    cudaGetSymbolAddress((void**)&p_ffl, d_ffl);
    cudaGetSymbolAddress((void**)&p_adjh, d_adjh);
    cudaGetSymbolAddress((void**)&p_adjl, d_adjl);
    cudaGetSymbolAddress((void**)&p_Xh,  d_Xh);
    cudaGetSymbolAddress((void**)&p_Xl,  d_Xl);
    cudaGetSymbolAddress((void**)&p_peTh, d_peTh);
    cudaGetSymbolAddress((void**)&p_peTl, d_peTl);
    cudaGetSymbolAddress((void**)&p_WT2h, d_WT2h);
    cudaGetSymbolAddress((void**)&p_WT2l, d_WT2l);
    cudaGetSymbolAddress((void**)&p_pe2h, d_pe2h);
    cudaGetSymbolAddress((void**)&p_pe2l, d_pe2l);
    cudaGetSymbolAddress((void**)&p_aggh, d_aggh);
    cudaGetSymbolAddress((void**)&p_aggl, d_aggl);
    cudaGetSymbolAddress((void**)&p_pwh, d_pwh);
    cudaGetSymbolAddress((void**)&p_pwl, d_pwl);
    cudaGetSymbolAddress((void**)&p_wph, d_wph);
    cudaGetSymbolAddress((void**)&p_wpl, d_wpl);

    cudaFuncSetAttribute(k_attn,     cudaFuncAttributeMaxDynamicSharedMemorySize, ATTN_SMEM);
    cudaFuncSetAttribute(tgemm,      cudaFuncAttributeMaxDynamicSharedMemorySize, TG_SMEM);
    cudaFuncSetAttribute(k_grouped2, cudaFuncAttributeMaxDynamicSharedMemorySize, GRP2_SMEM);

    // prep + splits
    k_mean<<<(BNN+255)/256, 256>>>(x_enc);
    k_peT<<<(DD*NN+255)/256, 256>>>(pe_raw, pos_w, pos_b);
    k_WT2<<<(DD*DD*DD+255)/256, 256>>>(wpool);
    k_conv<<<BNN, 128>>>(x_enc, conv_w);
    k_split<<<(NN*NN+255)/256, 256>>>(adj, p_adjh, p_adjl, NN*NN);
    k_split<<<64, 256>>>(wq,    p_wph+WPO_Q,  p_wpl+WPO_Q,  16384);
    k_split<<<64, 256>>>(wk,    p_wph+WPO_K,  p_wpl+WPO_K,  16384);
    k_split<<<64, 256>>>(wv,    p_wph+WPO_V,  p_wpl+WPO_V,  16384);
    k_split<<<64, 256>>>(wo,    p_wph+WPO_O,  p_wpl+WPO_O,  16384);
    k_split<<<256, 256>>>(ff_w1, p_wph+WPO_F1, p_wpl+WPO_F1, 65536);
    k_split<<<256, 256>>>(ff_w2, p_wph+WPO_F2, p_wpl+WPO_F2, 65536);

    // temporal transformer
    k_ln<<<ROWS/8, 256>>>(p_enc, ln1_g, ln1_b);
    tgemm<<<dim3(3, ROWS/128), 256, TG_SMEM>>>(p_hh, p_hl, p_wph+WPO_Q, p_wpl+WPO_Q,
        p_q, p_k, p_v, nullptr, nullptr, ROWS, 384, 128, nullptr, 6, 0);
    k_attn<<<BNN, 256, ATTN_SMEM>>>();
    tgemm<<<dim3(1, ROWS/128), 256, TG_SMEM>>>(p_qh, p_ql, p_wph+WPO_O, p_wpl+WPO_O,
        p_enc, nullptr, nullptr, nullptr, nullptr, ROWS, 128, 128, nullptr, 3, 0);
    k_ln<<<ROWS/8, 256>>>(p_enc, ln2_g, ln2_b);
    tgemm<<<dim3(4, ROWS/128), 256, TG_SMEM>>>(p_hh, p_hl, p_wph+WPO_F1, p_wpl+WPO_F1,
        nullptr, nullptr, nullptr, p_ffh, p_ffl, ROWS, 512, 128, ff_b1, 2, 0);
    tgemm<<<dim3(1, ROWS/128), 256, TG_SMEM>>>(p_ffh, p_ffl, p_wph+WPO_F2, p_wpl+WPO_F2,
        p_enc, nullptr, nullptr, nullptr, nullptr, ROWS, 128, 512, ff_b2, 3, 0);

    // spatial GCN
    k_transpose<<<dim3(94, BLL), 256>>>();
    tgemm<<<dim3(1, 24), 256, TG_SMEM>>>(p_adjh, p_adjl, p_peTh, p_peTl,
        nullptr, nullptr, nullptr, p_pe2h, p_pe2l, NN, 128, NN, nullptr, 5, 0);
    tgemm<<<dim3(128, 24), 256, TG_SMEM>>>(p_pe2h, p_pe2l, p_WT2h, p_WT2l,
        nullptr, nullptr, nullptr, p_pwh, p_pwl, NN, 16384, 128, nullptr, 5, 0);
    tgemm<<<dim3(24, 96), 256, TG_SMEM>>>(p_adjh, p_adjl, p_Xh, p_Xl,
        nullptr, nullptr, nullptr, p_aggh, p_aggl, NN, 12288, NN, nullptr, 5, 1);
    k_grouped2<<<NN, 256, GRP2_SMEM>>>();

    // groupnorm + head
    k_gnstats<<<BLL*4, 256>>>();
    k_final<<<BNN, 256>>>(gn_g, gn_b, p2_w, p2_b, p1_w, p1_b, out);
}